// round 14
// baseline (speedup 1.0000x reference)
#include <cuda_runtime.h>
#include <math.h>
#include <stdint.h>

#define B_ 128
#define S_ 256
#define E_ 300
#define H_ 300
#define G4 1200   // 4*H
#define DIV 601   // 2H+1
#define NM 38
#define KC 5
#define CHF 60
#define HPAD2 304
#define NB 8
#define TX_BYTES 9600

// ---------------- scratch ----------------------------------------------------
__device__ float g_mem [B_*S_*E_];
__device__ float g_xgf [B_*S_*G4];
__device__ float g_xgb [B_*S_*G4];
__device__ float g_outf[B_*S_*H_];
__device__ float g_outb[B_*S_*H_];
__device__ float g_ivec[B_*DIV];
__device__ int   g_mlen[B_], g_llen[B_], g_alen[B_];
__device__ int   g_perm[B_];

__device__ __forceinline__ float sigm(float x) { return 1.f / (1.f + expf(-x)); }

__device__ __forceinline__ uint32_t smem_u32(const void* p) {
    uint32_t a;
    asm("{ .reg .u64 t; cvta.to.shared.u64 t, %1; cvt.u32.u64 %0, t; }" : "=r"(a) : "l"(p));
    return a;
}
__device__ __forceinline__ unsigned long long pack2(float a, float b) {
    unsigned long long r;
    asm("mov.b64 %0, {%1,%2};" : "=l"(r) : "f"(a), "f"(b));
    return r;
}
__device__ __forceinline__ void fma2(unsigned long long& acc,
                                     unsigned long long a, unsigned long long b) {
    asm("fma.rn.f32x2 %0, %1, %2, %0;" : "+l"(acc) : "l"(a), "l"(b));
}
__device__ __forceinline__ float2 unpack2(unsigned long long v) {
    float2 f;
    asm("mov.b64 {%0,%1}, %2;" : "=f"(f.x), "=f"(f.y) : "l"(v));
    return f;
}
__device__ __forceinline__ void lds2u64(unsigned long long& a, unsigned long long& b,
                                        uint32_t addr) {
    asm volatile("ld.shared.v2.b64 {%0,%1}, [%2];" : "=l"(a), "=l"(b) : "r"(addr));
}
__device__ __forceinline__ void lds_v2u32(uint32_t& a, uint32_t& b, uint32_t addr) {
    asm volatile("ld.shared.v2.b32 {%0,%1}, [%2];" : "=r"(a), "=r"(b) : "r"(addr));
}
__device__ __forceinline__ float warpred(float v) {
#pragma unroll
    for (int o = 16; o > 0; o >>= 1) v += __shfl_down_sync(0xffffffffu, v, o);
    return v;
}
__device__ __forceinline__ void mbar_wait_cluster(uint32_t mbar, int parity) {
    uint32_t done;
    asm volatile(
        "{\n\t.reg .pred p;\n\t"
        "mbarrier.try_wait.parity.acquire.cluster.shared::cta.b64 p, [%1], %2;\n\t"
        "selp.b32 %0, 1, 0, p;\n\t}"
        : "=r"(done) : "r"(mbar), "r"((uint32_t)parity) : "memory");
    if (!done) {
        asm volatile(
            "{\n\t.reg .pred P1;\n\t"
            "WL_%=:\n\t"
            "mbarrier.try_wait.parity.acquire.cluster.shared::cta.b64 P1, [%0], %1, 0x989680;\n\t"
            "@P1 bra.uni WD_%=;\n\t"
            "bra.uni WL_%=;\n\t"
            "WD_%=:\n\t}"
            :: "r"(mbar), "r"((uint32_t)parity) : "memory");
    }
}
__device__ __forceinline__ uint32_t cvttf(float x) {
    uint32_t r;
    asm("cvt.rna.tf32.f32 %0, %1;" : "=r"(r) : "f"(x));
    return r;
}
__device__ __forceinline__ void mma_tf32(float* c, const uint32_t* a, const uint32_t* b) {
    asm volatile(
        "mma.sync.aligned.m16n8k8.row.col.f32.tf32.tf32.f32 "
        "{%0,%1,%2,%3},{%4,%5,%6,%7},{%8,%9},{%0,%1,%2,%3};"
        : "+f"(c[0]), "+f"(c[1]), "+f"(c[2]), "+f"(c[3])
        : "r"(a[0]), "r"(a[1]), "r"(a[2]), "r"(a[3]), "r"(b[0]), "r"(b[1]));
}

// ---------------- K0: lengths ------------------------------------------------
__global__ void k_prep(const int* __restrict__ text,
                       const int* __restrict__ aspect,
                       const int* __restrict__ leftc) {
    int b = blockIdx.x, t = threadIdx.x;
    int c1 = __syncthreads_count(text[b*S_ + t] != 0);
    int c2 = __syncthreads_count(leftc[b*S_ + t] != 0);
    int c3 = __syncthreads_count(t < 8 && aspect[b*8 + t] != 0);
    if (t == 0) { g_mlen[b] = c1; g_llen[b] = c2; g_alen[b] = c3; }
}

// ---------------- K0b: sort batches by length --------------------------------
__global__ void k_sort() {
    __shared__ int v[B_];
    int t = threadIdx.x;
    v[t] = (g_mlen[t] << 8) | t;
    __syncthreads();
    for (int k = 2; k <= B_; k <<= 1) {
        for (int j = k >> 1; j > 0; j >>= 1) {
            int ixj = t ^ j;
            if (ixj > t) {
                int a = v[t], b = v[ixj];
                bool up = ((t & k) == 0);
                if ((a > b) == up) { v[t] = b; v[ixj] = a; }
            }
            __syncthreads();
        }
    }
    g_perm[t] = v[t] & 255;
}

// ---------------- K1: embedding gather (flat float4 copy) --------------------
__global__ __launch_bounds__(256) void k_embed(const int* __restrict__ text,
                                               const float* __restrict__ emb) {
    int i = blockIdx.x * 256 + threadIdx.x;          // over B*S*75 float4s
    int r = i / 75, c = i - r * 75;
    int id = text[r];
    ((float4*)g_mem)[i] = ((const float4*)(emb + (size_t)id * E_))[c];
}

// ---------------- K2: xg GEMM via tf32 tensor cores --------------------------
// Pair-permuted smem: within each 8-col k-group, col j at pos (j&3)*2+(j>>2),
// so each fragment (k, k+4) pair is one ld.shared.v2.b32.
#define AST 36
#define GEMM_SMEM_U32 (2*128*AST + 2*64*AST)
#define GEMM_SMEM_BYTES  (GEMM_SMEM_U32*4)

__global__ __launch_bounds__(256, 3) void k_gemm_tc(
    const float* __restrict__ Wf, const float* __restrict__ bf,
    const float* __restrict__ Wb, const float* __restrict__ bb_) {
    extern __shared__ uint32_t smg[];
    uint32_t* As = smg;                    // [2][128][AST]  tf32 bits (permuted)
    uint32_t* Bs = smg + 2*128*AST;        // [2][64][AST]   tf32 bits (permuted)
    const int N = G4, K = E_;
    const float* A    = g_mem;
    const float* W    = blockIdx.z ? Wb  : Wf;
    const float* bias = blockIdx.z ? bb_ : bf;
    float* C          = blockIdx.z ? g_xgb : g_xgf;

    const int tid  = threadIdx.x;
    const int lane = tid & 31;
    const int warp = tid >> 5;
    const int wm_  = warp >> 1;
    const int wn_  = warp & 1;
    const int m0   = blockIdx.x * 128;
    const int n0   = blockIdx.y * 64;

    const int aRow[4] = { (tid+0*256)>>3, (tid+1*256)>>3, (tid+2*256)>>3, (tid+3*256)>>3 };
    const int aF4 [4] = { (tid+0*256)&7,  (tid+1*256)&7,  (tid+2*256)&7,  (tid+3*256)&7  };
    const int bRow[2] = { (tid+0*256)>>3, (tid+1*256)>>3 };
    const int bF4 [2] = { (tid+0*256)&7,  (tid+1*256)&7  };

    float4 rA[4], rB[2];
    auto ldChunk = [&](int c) {
        int kc0 = c * 32;
#pragma unroll
        for (int j = 0; j < 4; j++) {
            int kk = kc0 + aF4[j]*4;
            rA[j] = (kk < K) ? *(const float4*)(A + (size_t)(m0 + aRow[j]) * K + kk)
                             : make_float4(0.f,0.f,0.f,0.f);
        }
#pragma unroll
        for (int j = 0; j < 2; j++) {
            int kk = kc0 + bF4[j]*4;
            rB[j] = (kk < K && n0 + bRow[j] < N)
                    ? *(const float4*)(W + (size_t)(n0 + bRow[j]) * K + kk)
                    : make_float4(0.f,0.f,0.f,0.f);
        }
    };
    // permuted scatter: float4 of cols 4f..4f+3 -> base (f>>1)*8+(f&1), stride 2
    auto stChunk = [&](int buf) {
#pragma unroll
        for (int j = 0; j < 4; j++) {
            uint32_t* p = As + (size_t)buf*128*AST + aRow[j]*AST
                        + (aF4[j]>>1)*8 + (aF4[j]&1);
            p[0] = cvttf(rA[j].x); p[2] = cvttf(rA[j].y);
            p[4] = cvttf(rA[j].z); p[6] = cvttf(rA[j].w);
        }
#pragma unroll
        for (int j = 0; j < 2; j++) {
            uint32_t* p = Bs + (size_t)buf*64*AST + bRow[j]*AST
                        + (bF4[j]>>1)*8 + (bF4[j]&1);
            p[0] = cvttf(rB[j].x); p[2] = cvttf(rB[j].y);
            p[4] = cvttf(rB[j].z); p[6] = cvttf(rB[j].w);
        }
    };

    float acc[2][4][4];
#pragma unroll
    for (int i = 0; i < 2; i++)
#pragma unroll
        for (int j = 0; j < 4; j++)
#pragma unroll
            for (int k = 0; k < 4; k++) acc[i][j][k] = 0.f;

    ldChunk(0);
    stChunk(0);
    __syncthreads();

    const uint32_t As_u = smem_u32(As);
    const uint32_t Bs_u = smem_u32(Bs);

    for (int c = 0; c < 10; c++) {
        int cur = c & 1;
        if (c + 1 < 10) ldChunk(c + 1);
        const uint32_t abase = As_u + (uint32_t)cur*128*AST*4u;
        const uint32_t bbase = Bs_u + (uint32_t)cur*64*AST*4u;
#pragma unroll
        for (int ks = 0; ks < 4; ks++) {
            // fragment pair offset within row: ks*8 + 2*(lane&3)
            const uint32_t fo = (uint32_t)(ks*8 + 2*(lane & 3))*4u;
            uint32_t afr[2][4];
#pragma unroll
            for (int tm = 0; tm < 2; tm++) {
                int r = wm_*32 + tm*16 + (lane >> 2);
                lds_v2u32(afr[tm][0], afr[tm][2], abase + (uint32_t)r*AST*4u + fo);
                lds_v2u32(afr[tm][1], afr[tm][3], abase + (uint32_t)(r+8)*AST*4u + fo);
            }
            uint32_t bfr[4][2];
#pragma unroll
            for (int tn = 0; tn < 4; tn++) {
                int nn = wn_*32 + tn*8 + (lane >> 2);
                lds_v2u32(bfr[tn][0], bfr[tn][1], bbase + (uint32_t)nn*AST*4u + fo);
            }
#pragma unroll
            for (int tm = 0; tm < 2; tm++)
#pragma unroll
                for (int tn = 0; tn < 4; tn++)
                    mma_tf32(acc[tm][tn], afr[tm], bfr[tn]);
        }
        if (c + 1 < 10) stChunk(cur ^ 1);
        __syncthreads();
    }

#pragma unroll
    for (int tm = 0; tm < 2; tm++) {
        int r0 = m0 + wm_*32 + tm*16 + (lane >> 2);
#pragma unroll
        for (int tn = 0; tn < 4; tn++) {
            int cc = n0 + wn_*32 + tn*8 + 2*(lane & 3);
            if (cc < N) {
                float2 v0 = make_float2(acc[tm][tn][0] + bias[cc],
                                        acc[tm][tn][1] + bias[cc+1]);
                float2 v1 = make_float2(acc[tm][tn][2] + bias[cc],
                                        acc[tm][tn][3] + bias[cc+1]);
                *(float2*)(C + (size_t)r0 * N + cc)       = v0;
                *(float2*)(C + (size_t)(r0+8) * N + cc)   = v1;
            }
        }
    }
}

// ---------------- K3: clustered scan (R12-exact proven config) ---------------
#define SC8_FLOATS (2*NB*HPAD2 + NB*152 + 152*41 + 152)
#define SC8_BYTES  (SC8_FLOATS*4)

__global__ void __cluster_dims__(8,1,1) __launch_bounds__(768, 1)
k_scan8(const float* __restrict__ Whf, const float* __restrict__ bhf,
        const float* __restrict__ Whb, const float* __restrict__ bhb) {
    extern __shared__ float sm[];
    float* h_s   = sm;                        // [2][8][HPAD2]
    float* xg_s  = h_s + 2*NB*HPAD2;          // [8][152]
    float* g_s   = xg_s + NB*152;             // row*41 + bb*5 + kc
    float* bhh_s = g_s + 152*41;
    __shared__ __align__(8) unsigned long long mbar[2];
    __shared__ int len_s[NB], bset[NB];
    __shared__ int maxlen_s;

    const int rank = blockIdx.x;
    const int grp  = blockIdx.y;
    const int dir  = grp & 1;
    const int gi   = 15 - (grp >> 1);         // LPT order
    const int m0   = rank * NM;
    const int tid  = threadIdx.x;
    const bool act = tid < 760;
    const int kc   = act ? (tid / 152) : 0;
    const int row  = tid % 152;
    const int wg   = row / 38;                // gate-major: coalesced xg
    const int wm   = row - wg * 38;
    const bool wok = act && (m0 + wm < H_);

    const float* Whh = dir ? Whb : Whf;
    const float* bhh = dir ? bhb : bhf;
    const float* xg  = dir ? g_xgb : g_xgf;
    float* out       = dir ? g_outb : g_outf;

    if (tid < NB) {
        int b = g_perm[gi*NB + tid];
        bset[tid]  = b;
        len_s[tid] = g_mlen[b];
    }
    for (int i = tid; i < 2*NB*HPAD2; i += 768) h_s[i] = 0.f;
    if (tid < 152) {
        int g2 = tid / 38, m2 = tid - g2 * 38;
        bhh_s[tid] = (m0 + m2 < H_) ? bhh[g2*300 + m0 + m2] : 0.f;
    }
    const uint32_t mb_base = smem_u32(&mbar[0]);
    if (tid == 0) {
        asm volatile("mbarrier.init.shared.b64 [%0], %1;" :: "r"(mb_base),     "r"(1u) : "memory");
        asm volatile("mbarrier.init.shared.b64 [%0], %1;" :: "r"(mb_base + 8), "r"(1u) : "memory");
    }

    unsigned long long w2[30];
    {
        const float* wr = Whh + (size_t)(wg*300 + m0 + wm) * 300 + kc*CHF;
#pragma unroll
        for (int j = 0; j < 30; j++) {
            float2 v = make_float2(0.f, 0.f);
            if (wok) v = *(const float2*)(wr + 2*j);
            w2[j] = pack2(v.x, v.y);
        }
    }
    __syncthreads();
    if (tid == 0) {
        int mx = len_s[0];
        for (int i = 1; i < NB; i++) mx = max(mx, len_s[i]);
        maxlen_s = mx;
    }
    __syncthreads();
    const int maxlen = maxlen_s;

    asm volatile("barrier.cluster.arrive.aligned;" ::: "memory");
    asm volatile("barrier.cluster.wait.aligned;"   ::: "memory");

    const int p_bb0 = tid / 152;
    const int xcol  = wg*300 + m0 + wm;
    const bool xok  = (tid < 608) && (m0 + wm < H_);

    const int u_bb = tid & 7, u_m = tid >> 3;
    const bool uok = (tid < 304) && (m0 + u_m < H_);
    const int u_L  = len_s[u_bb & (NB-1)];
    const int u_b  = bset[u_bb & (NB-1)];
    const int mg   = m0 + u_m;
    float c_reg = 0.f;

    const uint32_t h_base = smem_u32(h_s);
    int buf = 0;
    int ph[2] = {0, 0};
    for (int t = 0; t < maxlen; t++) {
        const int pn = (t + 1) & 1;
        const uint32_t mb_n = mb_base + (uint32_t)pn * 8u;
        if (tid == 0) {
            asm volatile("mbarrier.arrive.expect_tx.shared.b64 _, [%0], %1;"
                         :: "r"(mb_n), "r"((uint32_t)TX_BYTES) : "memory");
        }
        float xv0 = 0.f, xv1 = 0.f;
        if (xok) {
            int L0 = len_s[p_bb0], L1 = len_s[p_bb0 + 4];
            int s0 = dir ? (L0 - 1 - t) : t; if (s0 < 0) s0 = 0;
            int s1 = dir ? (L1 - 1 - t) : t; if (s1 < 0) s1 = 0;
            xv0 = xg[((size_t)bset[p_bb0    ]*S_ + s0)*G4 + xcol];
            xv1 = xg[((size_t)bset[p_bb0 + 4]*S_ + s1)*G4 + xcol];
        }
        if (act) {
#pragma unroll
            for (int p = 0; p < 2; p++) {
                unsigned long long a0 = 0ull, a1 = 0ull, a2 = 0ull, a3 = 0ull;
                uint32_t hb = h_base + (uint32_t)((buf*NB + 4*p)*HPAD2 + kc*CHF)*4u;
#pragma unroll
                for (int j = 0; j < 15; j++) {
                    unsigned long long q0, q1;
                    lds2u64(q0, q1, hb + j*16);
                    fma2(a0, w2[2*j], q0); fma2(a0, w2[2*j+1], q1);
                    lds2u64(q0, q1, hb + HPAD2*4 + j*16);
                    fma2(a1, w2[2*j], q0); fma2(a1, w2[2*j+1], q1);
                    lds2u64(q0, q1, hb + 2*HPAD2*4 + j*16);
                    fma2(a2, w2[2*j], q0); fma2(a2, w2[2*j+1], q1);
                    lds2u64(q0, q1, hb + 3*HPAD2*4 + j*16);
                    fma2(a3, w2[2*j], q0); fma2(a3, w2[2*j+1], q1);
                }
                float2 f0 = unpack2(a0), f1 = unpack2(a1);
                float2 f2 = unpack2(a2), f3 = unpack2(a3);
                g_s[row*41 + (4*p+0)*5 + kc] = f0.x + f0.y;
                g_s[row*41 + (4*p+1)*5 + kc] = f1.x + f1.y;
                g_s[row*41 + (4*p+2)*5 + kc] = f2.x + f2.y;
                g_s[row*41 + (4*p+3)*5 + kc] = f3.x + f3.y;
            }
        }
        if (tid < 608) {
            xg_s[p_bb0*152 + row]       = xv0;
            xg_s[(p_bb0 + 4)*152 + row] = xv1;
        }
        __syncthreads();
        if (uok) {
            float gv[4];
#pragma unroll
            for (int g = 0; g < 4; g++) {
                int r2 = g*38 + u_m;
                float s_ = xg_s[u_bb*152 + r2] + bhh_s[r2];
#pragma unroll
                for (int k2 = 0; k2 < KC; k2++) s_ += g_s[r2*41 + u_bb*5 + k2];
                gv[g] = s_;
            }
            float hw;
            bool live = (t < u_L);
            if (live) {
                float ig = sigm(gv[0]), fg = sigm(gv[1]);
                float gt = tanhf(gv[2]), og = sigm(gv[3]);
                float cn = fg * c_reg + ig * gt;
                c_reg = cn;
                hw = og * tanhf(cn);
            } else {
                hw = h_s[(buf*NB + u_bb)*HPAD2 + mg];
            }
            int nb2 = buf ^ 1;
            uint32_t laddr = smem_u32(&h_s[(nb2*NB + u_bb)*HPAD2 + mg]);
            uint32_t hw_u  = __float_as_uint(hw);
#pragma unroll
            for (int r = 0; r < 8; r++) {
                uint32_t raddr, rmbar;
                asm volatile("mapa.shared::cluster.u32 %0, %1, %2;"
                             : "=r"(raddr) : "r"(laddr), "r"(r));
                asm volatile("mapa.shared::cluster.u32 %0, %1, %2;"
                             : "=r"(rmbar) : "r"(mb_n), "r"(r));
                asm volatile(
                    "st.async.shared::cluster.mbarrier::complete_tx::bytes.b32 [%0], %1, [%2];"
                    :: "r"(raddr), "r"(hw_u), "r"(rmbar) : "memory");
            }
            if (live) {
                int s = dir ? (u_L - 1 - t) : t;
                out[((size_t)u_b*S_ + s)*H_ + mg] = hw;
            } else {
                out[((size_t)u_b*S_ + t)*H_ + mg] = 0.f;
            }
        }
        mbar_wait_cluster(mb_n, ph[pn]);
        ph[pn] ^= 1;
        buf ^= 1;
    }
    for (int t = maxlen; t < S_; t++)
        if (uok)
            out[((size_t)u_b*S_ + t)*H_ + mg] = 0.f;
}

// ---------------- K4: attention ----------------------------------------------
__global__ __launch_bounds__(256) void k_attn(const float* __restrict__ attW) {
    __shared__ __align__(16) float attw_s[1204];
    __shared__ float aw_s[256];
    __shared__ float au_s[256];
    __shared__ float red[256];
    int b = blockIdx.x, t = threadIdx.x;
    for (int i = t; i < 1201; i += 256) attw_s[i] = attW[i];
    __syncthreads();

    float ml = (float)g_mlen[b], ll = (float)g_llen[b], al = (float)g_alen[b];
    float pos = (float)t;
    float w, u;
    if (pos < ll)                       { w = 1.f - (ll - pos) / ml;            u = pos - ll; }
    else if (pos >= ll + al && pos < ml){ w = 1.f - (pos - ll - al + 1.f) / ml; u = pos - ll - al + 1.f; }
    else                                { w = 1.f; u = 0.f; }

    const float4* rf = (const float4*)(g_outf + ((size_t)b * S_ + t) * H_);
    const float4* rb = (const float4*)(g_outb + ((size_t)b * S_ + t) * H_);
    float dot = 0.f;
#pragma unroll 5
    for (int k = 0; k < 75; k++) {
        float4 a = rf[k]; float4 wv = *(const float4*)&attw_s[4 * k];
        dot += a.x*wv.x + a.y*wv.y + a.z*wv.z + a.w*wv.w;
        float4 c = rb[k]; float4 wv2 = *(const float4*)&attw_s[300 + 4 * k];
        dot += c.x*wv2.x + c.y*wv2.y + c.z*wv2.z + c.w*wv2.w;
    }
    float score = w * dot + u * attw_s[600];

    red[t] = score; __syncthreads();
    for (int off = 128; off > 0; off >>= 1) {
        if (t < off) red[t] = fmaxf(red[t], red[t + off]);
        __syncthreads();
    }
    float mx = red[0]; __syncthreads();
    float e = expf(score - mx);
    red[t] = e; __syncthreads();
    for (int off = 128; off > 0; off >>= 1) {
        if (t < off) red[t] += red[t + off];
        __syncthreads();
    }
    float alpha = e / red[0];
    aw_s[t] = alpha * w;
    au_s[t] = alpha * u;
    __syncthreads();

    for (int d = t; d < DIV; d += 256) {
        float acc = 0.f;
        if (d < 300) {
            const float* p = g_outf + (size_t)b * S_ * H_ + d;
            for (int s = 0; s < S_; s++) acc += aw_s[s] * p[(size_t)s * H_];
        } else if (d < 600) {
            const float* p = g_outb + (size_t)b * S_ * H_ + (d - 300);
            for (int s = 0; s < S_; s++) acc += aw_s[s] * p[(size_t)s * H_];
        } else {
            for (int s = 0; s < S_; s++) acc += au_s[s];
        }
        g_ivec[b * DIV + d] = acc;
    }
}

// ---------------- K5: GRU hops + dense -------------------------------------
__global__ __launch_bounds__(384) void k_final2(
    const float* __restrict__ Wih, const float* __restrict__ Whh,
    const float* __restrict__ bih, const float* __restrict__ bhh,
    const float* __restrict__ dW,  const float* __restrict__ db,
    float* __restrict__ outp) {
    __shared__ float iv_s[DIV];
    __shared__ float et_s[300];
    __shared__ float gi_s[900];
    __shared__ float gh_s[900];
    int b = blockIdx.x, t = threadIdx.x;
    int w = t >> 5, lane = t & 31;

    for (int i = t; i < DIV; i += 384) iv_s[i] = g_ivec[b * DIV + i];
    if (t < 300) et_s[t] = 0.f;
    __syncthreads();

    for (int row = w; row < 900; row += 12) {
        const float* wp = Wih + (size_t)row * DIV;
        float acc = 0.f;
        for (int k = lane; k < DIV; k += 32) acc += wp[k] * iv_s[k];
        acc = warpred(acc);
        if (lane == 0) gi_s[row] = acc + bih[row];
    }
    __syncthreads();

    for (int hop = 0; hop < 3; hop++) {
        for (int row = w; row < 900; row += 12) {
            const float* wp = Whh + (size_t)row * 300;
            float acc = 0.f;
#pragma unroll 2
            for (int k = lane; k < 300; k += 32) acc += wp[k] * et_s[k];
            acc = warpred(acc);
            if (lane == 0) gh_s[row] = acc + bhh[row];
        }
        __syncthreads();
        float newet = 0.f;
        if (t < 300) {
            float r = sigm(gi_s[t]       + gh_s[t]);
            float z = sigm(gi_s[300 + t] + gh_s[300 + t]);
            float n = tanhf(gi_s[600 + t] + r * gh_s[600 + t]);
            newet = (1.f - z) * n + z * et_s[t];
        }
        __syncthreads();
        if (t < 300) et_s[t] = newet;
        __syncthreads();
    }

    if (w < 3) {
        const float* wp = dW + w * 300;
        float acc = 0.f;
        for (int k = lane; k < 300; k += 32) acc += wp[k] * et_s[k];
        acc = warpred(acc);
        if (lane == 0) outp[b * 3 + w] = acc + db[w];
    }
}

// ---------------- launch -----------------------------------------------------
extern "C" void kernel_launch(void* const* d_in, const int* in_sizes, int n_in,
                              void* d_out, int out_size) {
    const int*   text      = (const int*)  d_in[0];
    const int*   aspect    = (const int*)  d_in[1];
    const int*   leftc     = (const int*)  d_in[2];
    const float* embedding = (const float*)d_in[3];
    const float* Wih_f     = (const float*)d_in[4];
    const float* Whh_f     = (const float*)d_in[5];
    const float* bih_f     = (const float*)d_in[6];
    const float* bhh_f     = (const float*)d_in[7];
    const float* Wih_b     = (const float*)d_in[8];
    const float* Whh_b     = (const float*)d_in[9];
    const float* bih_b     = (const float*)d_in[10];
    const float* bhh_b     = (const float*)d_in[11];
    const float* att_W     = (const float*)d_in[12];
    const float* gru_Wih   = (const float*)d_in[14];
    const float* gru_Whh   = (const float*)d_in[15];
    const float* gru_bih   = (const float*)d_in[16];
    const float* gru_bhh   = (const float*)d_in[17];
    const float* dense_W   = (const float*)d_in[18];
    const float* dense_b   = (const float*)d_in[19];
    float* outp = (float*)d_out;

    cudaFuncSetAttribute(k_scan8, cudaFuncAttributeMaxDynamicSharedMemorySize,
                         SC8_BYTES);
    cudaFuncSetAttribute(k_gemm_tc, cudaFuncAttributeMaxDynamicSharedMemorySize,
                         GEMM_SMEM_BYTES);

    k_prep<<<B_, 256>>>(text, aspect, leftc);
    k_sort<<<1, B_>>>();
    k_embed<<<(B_ * S_ * 75) / 256, 256>>>(text, embedding);
    k_gemm_tc<<<dim3(B_ * S_ / 128, (G4 + 63) / 64, 2), 256, GEMM_SMEM_BYTES>>>(
        Wih_f, bih_f, Wih_b, bih_b);
    k_scan8<<<dim3(8, 32), 768, SC8_BYTES>>>(Whh_f, bhh_f, Whh_b, bhh_b);
    k_attn<<<B_, 256>>>(att_W);
    k_final2<<<B_, 384>>>(gru_Wih, gru_Whh, gru_bih, gru_bhh, dense_W, dense_b, outp);
}

// round 15
// speedup vs baseline: 1.0296x; 1.0296x over previous
#include <cuda_runtime.h>
#include <math.h>
#include <stdint.h>

#define B_ 128
#define S_ 256
#define E_ 300
#define H_ 300
#define G4 1200   // 4*H
#define DIV 601   // 2H+1
#define NM 38
#define KC 5
#define CHF 60
#define HPAD2 304
#define NB 8
#define TX_BYTES 9600

// ---------------- scratch ----------------------------------------------------
__device__ float g_mem [B_*S_*E_];
__device__ float g_xgf [B_*S_*G4];
__device__ float g_xgb [B_*S_*G4];
__device__ float g_outf[B_*S_*H_];
__device__ float g_outb[B_*S_*H_];
__device__ float g_ivec[B_*DIV];
__device__ int   g_mlen[B_], g_llen[B_], g_alen[B_];
__device__ int   g_perm[B_];

// fast activations: __expf (MUFU ex2, ~1e-7 rel err) + fast divide
__device__ __forceinline__ float sigm_f(float x) {
    return __fdividef(1.f, 1.f + __expf(-x));
}
__device__ __forceinline__ float tanh_f(float x) {
    return 1.f - __fdividef(2.f, __expf(2.f * x) + 1.f);
}

__device__ __forceinline__ uint32_t smem_u32(const void* p) {
    uint32_t a;
    asm("{ .reg .u64 t; cvta.to.shared.u64 t, %1; cvt.u32.u64 %0, t; }" : "=r"(a) : "l"(p));
    return a;
}
__device__ __forceinline__ unsigned long long pack2(float a, float b) {
    unsigned long long r;
    asm("mov.b64 %0, {%1,%2};" : "=l"(r) : "f"(a), "f"(b));
    return r;
}
__device__ __forceinline__ void fma2(unsigned long long& acc,
                                     unsigned long long a, unsigned long long b) {
    asm("fma.rn.f32x2 %0, %1, %2, %0;" : "+l"(acc) : "l"(a), "l"(b));
}
__device__ __forceinline__ float2 unpack2(unsigned long long v) {
    float2 f;
    asm("mov.b64 {%0,%1}, %2;" : "=f"(f.x), "=f"(f.y) : "l"(v));
    return f;
}
__device__ __forceinline__ void lds2u64(unsigned long long& a, unsigned long long& b,
                                        uint32_t addr) {
    asm volatile("ld.shared.v2.b64 {%0,%1}, [%2];" : "=l"(a), "=l"(b) : "r"(addr));
}
__device__ __forceinline__ float warpred(float v) {
#pragma unroll
    for (int o = 16; o > 0; o >>= 1) v += __shfl_down_sync(0xffffffffu, v, o);
    return v;
}
__device__ __forceinline__ void mbar_wait_cluster(uint32_t mbar, int parity) {
    uint32_t done;
    asm volatile(
        "{\n\t.reg .pred p;\n\t"
        "mbarrier.try_wait.parity.acquire.cluster.shared::cta.b64 p, [%1], %2;\n\t"
        "selp.b32 %0, 1, 0, p;\n\t}"
        : "=r"(done) : "r"(mbar), "r"((uint32_t)parity) : "memory");
    if (!done) {
        asm volatile(
            "{\n\t.reg .pred P1;\n\t"
            "WL_%=:\n\t"
            "mbarrier.try_wait.parity.acquire.cluster.shared::cta.b64 P1, [%0], %1, 0x989680;\n\t"
            "@P1 bra.uni WD_%=;\n\t"
            "bra.uni WL_%=;\n\t"
            "WD_%=:\n\t}"
            :: "r"(mbar), "r"((uint32_t)parity) : "memory");
    }
}
__device__ __forceinline__ uint32_t cvttf(float x) {
    uint32_t r;
    asm("cvt.rna.tf32.f32 %0, %1;" : "=r"(r) : "f"(x));
    return r;
}
__device__ __forceinline__ void mma_tf32(float* c, const uint32_t* a, const uint32_t* b) {
    asm volatile(
        "mma.sync.aligned.m16n8k8.row.col.f32.tf32.tf32.f32 "
        "{%0,%1,%2,%3},{%4,%5,%6,%7},{%8,%9},{%0,%1,%2,%3};"
        : "+f"(c[0]), "+f"(c[1]), "+f"(c[2]), "+f"(c[3])
        : "r"(a[0]), "r"(a[1]), "r"(a[2]), "r"(a[3]), "r"(b[0]), "r"(b[1]));
}

// ---------------- K0: lengths ------------------------------------------------
__global__ void k_prep(const int* __restrict__ text,
                       const int* __restrict__ aspect,
                       const int* __restrict__ leftc) {
    int b = blockIdx.x, t = threadIdx.x;
    int c1 = __syncthreads_count(text[b*S_ + t] != 0);
    int c2 = __syncthreads_count(leftc[b*S_ + t] != 0);
    int c3 = __syncthreads_count(t < 8 && aspect[b*8 + t] != 0);
    if (t == 0) { g_mlen[b] = c1; g_llen[b] = c2; g_alen[b] = c3; }
}

// ---------------- K0b: sort batches by length --------------------------------
__global__ void k_sort() {
    __shared__ int v[B_];
    int t = threadIdx.x;
    v[t] = (g_mlen[t] << 8) | t;
    __syncthreads();
    for (int k = 2; k <= B_; k <<= 1) {
        for (int j = k >> 1; j > 0; j >>= 1) {
            int ixj = t ^ j;
            if (ixj > t) {
                int a = v[t], b = v[ixj];
                bool up = ((t & k) == 0);
                if ((a > b) == up) { v[t] = b; v[ixj] = a; }
            }
            __syncthreads();
        }
    }
    g_perm[t] = v[t] & 255;
}

// ---------------- K1: embedding gather (flat float4 copy) --------------------
__global__ __launch_bounds__(256) void k_embed(const int* __restrict__ text,
                                               const float* __restrict__ emb) {
    int i = blockIdx.x * 256 + threadIdx.x;          // over B*S*75 float4s
    int r = i / 75, c = i - r * 75;
    int id = text[r];
    ((float4*)g_mem)[i] = ((const float4*)(emb + (size_t)id * E_))[c];
}

// ---------------- K2: xg GEMM via tf32 tensor cores (R12-exact) --------------
#define AST 36
#define GEMM_SMEM_U32 (2*128*AST + 2*64*AST)
#define GEMM_SMEM_BYTES  (GEMM_SMEM_U32*4)

__global__ __launch_bounds__(256, 3) void k_gemm_tc(
    const float* __restrict__ Wf, const float* __restrict__ bf,
    const float* __restrict__ Wb, const float* __restrict__ bb_) {
    extern __shared__ uint32_t smg[];
    uint32_t* As = smg;                    // [2][128][AST]  tf32 bits
    uint32_t* Bs = smg + 2*128*AST;        // [2][64][AST]   tf32 bits
    const int N = G4, K = E_;
    const float* A    = g_mem;
    const float* W    = blockIdx.z ? Wb  : Wf;
    const float* bias = blockIdx.z ? bb_ : bf;
    float* C          = blockIdx.z ? g_xgb : g_xgf;

    const int tid  = threadIdx.x;
    const int lane = tid & 31;
    const int warp = tid >> 5;
    const int wm_  = warp >> 1;
    const int wn_  = warp & 1;
    const int m0   = blockIdx.x * 128;
    const int n0   = blockIdx.y * 64;

    const int aRow[4] = { (tid+0*256)>>3, (tid+1*256)>>3, (tid+2*256)>>3, (tid+3*256)>>3 };
    const int aF4 [4] = { (tid+0*256)&7,  (tid+1*256)&7,  (tid+2*256)&7,  (tid+3*256)&7  };
    const int bRow[2] = { (tid+0*256)>>3, (tid+1*256)>>3 };
    const int bF4 [2] = { (tid+0*256)&7,  (tid+1*256)&7  };

    float4 rA[4], rB[2];
    auto ldChunk = [&](int c) {
        int kc0 = c * 32;
#pragma unroll
        for (int j = 0; j < 4; j++) {
            int kk = kc0 + aF4[j]*4;
            rA[j] = (kk < K) ? *(const float4*)(A + (size_t)(m0 + aRow[j]) * K + kk)
                             : make_float4(0.f,0.f,0.f,0.f);
        }
#pragma unroll
        for (int j = 0; j < 2; j++) {
            int kk = kc0 + bF4[j]*4;
            rB[j] = (kk < K && n0 + bRow[j] < N)
                    ? *(const float4*)(W + (size_t)(n0 + bRow[j]) * K + kk)
                    : make_float4(0.f,0.f,0.f,0.f);
        }
    };
    auto stChunk = [&](int buf) {
#pragma unroll
        for (int j = 0; j < 4; j++) {
            uint4 t4 = make_uint4(cvttf(rA[j].x), cvttf(rA[j].y),
                                  cvttf(rA[j].z), cvttf(rA[j].w));
            *(uint4*)(As + (size_t)buf*128*AST + aRow[j]*AST + aF4[j]*4) = t4;
        }
#pragma unroll
        for (int j = 0; j < 2; j++) {
            uint4 t4 = make_uint4(cvttf(rB[j].x), cvttf(rB[j].y),
                                  cvttf(rB[j].z), cvttf(rB[j].w));
            *(uint4*)(Bs + (size_t)buf*64*AST + bRow[j]*AST + bF4[j]*4) = t4;
        }
    };

    float acc[2][4][4];
#pragma unroll
    for (int i = 0; i < 2; i++)
#pragma unroll
        for (int j = 0; j < 4; j++)
#pragma unroll
            for (int k = 0; k < 4; k++) acc[i][j][k] = 0.f;

    ldChunk(0);
    stChunk(0);
    __syncthreads();

    for (int c = 0; c < 10; c++) {
        int cur = c & 1;
        if (c + 1 < 10) ldChunk(c + 1);
        const uint32_t* Ab = As + (size_t)cur*128*AST;
        const uint32_t* Bb = Bs + (size_t)cur*64*AST;
#pragma unroll
        for (int ks = 0; ks < 4; ks++) {
            int kk = ks * 8;
            uint32_t afr[2][4];
#pragma unroll
            for (int tm = 0; tm < 2; tm++) {
                int r  = wm_*32 + tm*16 + (lane >> 2);
                int cc = kk + (lane & 3);
                afr[tm][0] = Ab[r*AST + cc];
                afr[tm][1] = Ab[(r+8)*AST + cc];
                afr[tm][2] = Ab[r*AST + cc + 4];
                afr[tm][3] = Ab[(r+8)*AST + cc + 4];
            }
            uint32_t bfr[4][2];
#pragma unroll
            for (int tn = 0; tn < 4; tn++) {
                int nn = wn_*32 + tn*8 + (lane >> 2);
                int ck = kk + (lane & 3);
                bfr[tn][0] = Bb[nn*AST + ck];
                bfr[tn][1] = Bb[nn*AST + ck + 4];
            }
#pragma unroll
            for (int tm = 0; tm < 2; tm++)
#pragma unroll
                for (int tn = 0; tn < 4; tn++)
                    mma_tf32(acc[tm][tn], afr[tm], bfr[tn]);
        }
        if (c + 1 < 10) stChunk(cur ^ 1);
        __syncthreads();
    }

#pragma unroll
    for (int tm = 0; tm < 2; tm++) {
        int r0 = m0 + wm_*32 + tm*16 + (lane >> 2);
#pragma unroll
        for (int tn = 0; tn < 4; tn++) {
            int cc = n0 + wn_*32 + tn*8 + 2*(lane & 3);
            if (cc < N) {
                float2 v0 = make_float2(acc[tm][tn][0] + bias[cc],
                                        acc[tm][tn][1] + bias[cc+1]);
                float2 v1 = make_float2(acc[tm][tn][2] + bias[cc],
                                        acc[tm][tn][3] + bias[cc+1]);
                *(float2*)(C + (size_t)r0 * N + cc)       = v0;
                *(float2*)(C + (size_t)(r0+8) * N + cc)   = v1;
            }
        }
    }
}

// ---------------- K3: clustered scan (R12 structure, fast activations) -------
#define SC8_FLOATS (2*NB*HPAD2 + NB*152 + 152*41 + 152)
#define SC8_BYTES  (SC8_FLOATS*4)

__global__ void __cluster_dims__(8,1,1) __launch_bounds__(768, 1)
k_scan8(const float* __restrict__ Whf, const float* __restrict__ bhf,
        const float* __restrict__ Whb, const float* __restrict__ bhb) {
    extern __shared__ float sm[];
    float* h_s   = sm;                        // [2][8][HPAD2]
    float* xg_s  = h_s + 2*NB*HPAD2;          // [8][152]
    float* g_s   = xg_s + NB*152;             // row*41 + bb*5 + kc
    float* bhh_s = g_s + 152*41;
    __shared__ __align__(8) unsigned long long mbar[2];
    __shared__ int len_s[NB], bset[NB];
    __shared__ int maxlen_s;

    const int rank = blockIdx.x;
    const int grp  = blockIdx.y;
    const int dir  = grp & 1;
    const int gi   = 15 - (grp >> 1);         // LPT order
    const int m0   = rank * NM;
    const int tid  = threadIdx.x;
    const bool act = tid < 760;
    const int kc   = act ? (tid / 152) : 0;
    const int row  = tid % 152;
    const int wg   = row / 38;                // gate-major: coalesced xg
    const int wm   = row - wg * 38;
    const bool wok = act && (m0 + wm < H_);

    const float* Whh = dir ? Whb : Whf;
    const float* bhh = dir ? bhb : bhf;
    const float* xg  = dir ? g_xgb : g_xgf;
    float* out       = dir ? g_outb : g_outf;

    if (tid < NB) {
        int b = g_perm[gi*NB + tid];
        bset[tid]  = b;
        len_s[tid] = g_mlen[b];
    }
    for (int i = tid; i < 2*NB*HPAD2; i += 768) h_s[i] = 0.f;
    if (tid < 152) {
        int g2 = tid / 38, m2 = tid - g2 * 38;
        bhh_s[tid] = (m0 + m2 < H_) ? bhh[g2*300 + m0 + m2] : 0.f;
    }
    const uint32_t mb_base = smem_u32(&mbar[0]);
    if (tid == 0) {
        asm volatile("mbarrier.init.shared.b64 [%0], %1;" :: "r"(mb_base),     "r"(1u) : "memory");
        asm volatile("mbarrier.init.shared.b64 [%0], %1;" :: "r"(mb_base + 8), "r"(1u) : "memory");
    }

    unsigned long long w2[30];
    {
        const float* wr = Whh + (size_t)(wg*300 + m0 + wm) * 300 + kc*CHF;
#pragma unroll
        for (int j = 0; j < 30; j++) {
            float2 v = make_float2(0.f, 0.f);
            if (wok) v = *(const float2*)(wr + 2*j);
            w2[j] = pack2(v.x, v.y);
        }
    }
    __syncthreads();
    if (tid == 0) {
        int mx = len_s[0];
        for (int i = 1; i < NB; i++) mx = max(mx, len_s[i]);
        maxlen_s = mx;
    }
    __syncthreads();
    const int maxlen = maxlen_s;

    asm volatile("barrier.cluster.arrive.aligned;" ::: "memory");
    asm volatile("barrier.cluster.wait.aligned;"   ::: "memory");

    const int p_bb0 = tid / 152;
    const int xcol  = wg*300 + m0 + wm;
    const bool xok  = (tid < 608) && (m0 + wm < H_);

    const int u_bb = tid & 7, u_m = tid >> 3;
    const bool uok = (tid < 304) && (m0 + u_m < H_);
    const int u_L  = len_s[u_bb & (NB-1)];
    const int u_b  = bset[u_bb & (NB-1)];
    const int mg   = m0 + u_m;
    float c_reg = 0.f;

    const uint32_t h_base = smem_u32(h_s);
    int buf = 0;
    int ph[2] = {0, 0};
    for (int t = 0; t < maxlen; t++) {
        const int pn = (t + 1) & 1;
        const uint32_t mb_n = mb_base + (uint32_t)pn * 8u;
        if (tid == 0) {
            asm volatile("mbarrier.arrive.expect_tx.shared.b64 _, [%0], %1;"
                         :: "r"(mb_n), "r"((uint32_t)TX_BYTES) : "memory");
        }
        float xv0 = 0.f, xv1 = 0.f;
        if (xok) {
            int L0 = len_s[p_bb0], L1 = len_s[p_bb0 + 4];
            int s0 = dir ? (L0 - 1 - t) : t; if (s0 < 0) s0 = 0;
            int s1 = dir ? (L1 - 1 - t) : t; if (s1 < 0) s1 = 0;
            xv0 = xg[((size_t)bset[p_bb0    ]*S_ + s0)*G4 + xcol];
            xv1 = xg[((size_t)bset[p_bb0 + 4]*S_ + s1)*G4 + xcol];
        }
        if (act) {
#pragma unroll
            for (int p = 0; p < 2; p++) {
                unsigned long long a0 = 0ull, a1 = 0ull, a2 = 0ull, a3 = 0ull;
                uint32_t hb = h_base + (uint32_t)((buf*NB + 4*p)*HPAD2 + kc*CHF)*4u;
#pragma unroll
                for (int j = 0; j < 15; j++) {
                    unsigned long long q0, q1;
                    lds2u64(q0, q1, hb + j*16);
                    fma2(a0, w2[2*j], q0); fma2(a0, w2[2*j+1], q1);
                    lds2u64(q0, q1, hb + HPAD2*4 + j*16);
                    fma2(a1, w2[2*j], q0); fma2(a1, w2[2*j+1], q1);
                    lds2u64(q0, q1, hb + 2*HPAD2*4 + j*16);
                    fma2(a2, w2[2*j], q0); fma2(a2, w2[2*j+1], q1);
                    lds2u64(q0, q1, hb + 3*HPAD2*4 + j*16);
                    fma2(a3, w2[2*j], q0); fma2(a3, w2[2*j+1], q1);
                }
                float2 f0 = unpack2(a0), f1 = unpack2(a1);
                float2 f2 = unpack2(a2), f3 = unpack2(a3);
                g_s[row*41 + (4*p+0)*5 + kc] = f0.x + f0.y;
                g_s[row*41 + (4*p+1)*5 + kc] = f1.x + f1.y;
                g_s[row*41 + (4*p+2)*5 + kc] = f2.x + f2.y;
                g_s[row*41 + (4*p+3)*5 + kc] = f3.x + f3.y;
            }
        }
        if (tid < 608) {
            xg_s[p_bb0*152 + row]       = xv0;
            xg_s[(p_bb0 + 4)*152 + row] = xv1;
        }
        __syncthreads();
        if (uok) {
            float gv[4];
#pragma unroll
            for (int g = 0; g < 4; g++) {
                int r2 = g*38 + u_m;
                float s_ = xg_s[u_bb*152 + r2] + bhh_s[r2];
#pragma unroll
                for (int k2 = 0; k2 < KC; k2++) s_ += g_s[r2*41 + u_bb*5 + k2];
                gv[g] = s_;
            }
            float hw;
            bool live = (t < u_L);
            if (live) {
                float ig = sigm_f(gv[0]), fg = sigm_f(gv[1]);
                float gt = tanh_f(gv[2]), og = sigm_f(gv[3]);
                float cn = fg * c_reg + ig * gt;
                c_reg = cn;
                hw = og * tanh_f(cn);
            } else {
                hw = h_s[(buf*NB + u_bb)*HPAD2 + mg];
            }
            int nb2 = buf ^ 1;
            uint32_t laddr = smem_u32(&h_s[(nb2*NB + u_bb)*HPAD2 + mg]);
            uint32_t hw_u  = __float_as_uint(hw);
#pragma unroll
            for (int r = 0; r < 8; r++) {
                uint32_t raddr, rmbar;
                asm volatile("mapa.shared::cluster.u32 %0, %1, %2;"
                             : "=r"(raddr) : "r"(laddr), "r"(r));
                asm volatile("mapa.shared::cluster.u32 %0, %1, %2;"
                             : "=r"(rmbar) : "r"(mb_n), "r"(r));
                asm volatile(
                    "st.async.shared::cluster.mbarrier::complete_tx::bytes.b32 [%0], %1, [%2];"
                    :: "r"(raddr), "r"(hw_u), "r"(rmbar) : "memory");
            }
            if (live) {
                int s = dir ? (u_L - 1 - t) : t;
                out[((size_t)u_b*S_ + s)*H_ + mg] = hw;
            } else {
                out[((size_t)u_b*S_ + t)*H_ + mg] = 0.f;
            }
        }
        mbar_wait_cluster(mb_n, ph[pn]);
        ph[pn] ^= 1;
        buf ^= 1;
    }
    for (int t = maxlen; t < S_; t++)
        if (uok)
            out[((size_t)u_b*S_ + t)*H_ + mg] = 0.f;
}

// ---------------- K4: attention ----------------------------------------------
__global__ __launch_bounds__(256) void k_attn(const float* __restrict__ attW) {
    __shared__ __align__(16) float attw_s[1204];
    __shared__ float aw_s[256];
    __shared__ float au_s[256];
    __shared__ float red[256];
    int b = blockIdx.x, t = threadIdx.x;
    for (int i = t; i < 1201; i += 256) attw_s[i] = attW[i];
    __syncthreads();

    float ml = (float)g_mlen[b], ll = (float)g_llen[b], al = (float)g_alen[b];
    float pos = (float)t;
    float w, u;
    if (pos < ll)                       { w = 1.f - (ll - pos) / ml;            u = pos - ll; }
    else if (pos >= ll + al && pos < ml){ w = 1.f - (pos - ll - al + 1.f) / ml; u = pos - ll - al + 1.f; }
    else                                { w = 1.f; u = 0.f; }

    const float4* rf = (const float4*)(g_outf + ((size_t)b * S_ + t) * H_);
    const float4* rb = (const float4*)(g_outb + ((size_t)b * S_ + t) * H_);
    float dot = 0.f;
#pragma unroll 5
    for (int k = 0; k < 75; k++) {
        float4 a = rf[k]; float4 wv = *(const float4*)&attw_s[4 * k];
        dot += a.x*wv.x + a.y*wv.y + a.z*wv.z + a.w*wv.w;
        float4 c = rb[k]; float4 wv2 = *(const float4*)&attw_s[300 + 4 * k];
        dot += c.x*wv2.x + c.y*wv2.y + c.z*wv2.z + c.w*wv2.w;
    }
    float score = w * dot + u * attw_s[600];

    red[t] = score; __syncthreads();
    for (int off = 128; off > 0; off >>= 1) {
        if (t < off) red[t] = fmaxf(red[t], red[t + off]);
        __syncthreads();
    }
    float mx = red[0]; __syncthreads();
    float e = expf(score - mx);
    red[t] = e; __syncthreads();
    for (int off = 128; off > 0; off >>= 1) {
        if (t < off) red[t] += red[t + off];
        __syncthreads();
    }
    float alpha = e / red[0];
    aw_s[t] = alpha * w;
    au_s[t] = alpha * u;
    __syncthreads();

    for (int d = t; d < DIV; d += 256) {
        float acc = 0.f;
        if (d < 300) {
            const float* p = g_outf + (size_t)b * S_ * H_ + d;
            for (int s = 0; s < S_; s++) acc += aw_s[s] * p[(size_t)s * H_];
        } else if (d < 600) {
            const float* p = g_outb + (size_t)b * S_ * H_ + (d - 300);
            for (int s = 0; s < S_; s++) acc += aw_s[s] * p[(size_t)s * H_];
        } else {
            for (int s = 0; s < S_; s++) acc += au_s[s];
        }
        g_ivec[b * DIV + d] = acc;
    }
}

// ---------------- K5: GRU hops + dense (fast activations) -------------------
__global__ __launch_bounds__(384) void k_final2(
    const float* __restrict__ Wih, const float* __restrict__ Whh,
    const float* __restrict__ bih, const float* __restrict__ bhh,
    const float* __restrict__ dW,  const float* __restrict__ db,
    float* __restrict__ outp) {
    __shared__ float iv_s[DIV];
    __shared__ float et_s[300];
    __shared__ float gi_s[900];
    __shared__ float gh_s[900];
    int b = blockIdx.x, t = threadIdx.x;
    int w = t >> 5, lane = t & 31;

    for (int i = t; i < DIV; i += 384) iv_s[i] = g_ivec[b * DIV + i];
    if (t < 300) et_s[t] = 0.f;
    __syncthreads();

    for (int row = w; row < 900; row += 12) {
        const float* wp = Wih + (size_t)row * DIV;
        float acc = 0.f;
        for (int k = lane; k < DIV; k += 32) acc += wp[k] * iv_s[k];
        acc = warpred(acc);
        if (lane == 0) gi_s[row] = acc + bih[row];
    }
    __syncthreads();

    for (int hop = 0; hop < 3; hop++) {
        for (int row = w; row < 900; row += 12) {
            const float* wp = Whh + (size_t)row * 300;
            float acc = 0.f;
#pragma unroll 2
            for (int k = lane; k < 300; k += 32) acc += wp[k] * et_s[k];
            acc = warpred(acc);
            if (lane == 0) gh_s[row] = acc + bhh[row];
        }
        __syncthreads();
        float newet = 0.f;
        if (t < 300) {
            float r = sigm_f(gi_s[t]       + gh_s[t]);
            float z = sigm_f(gi_s[300 + t] + gh_s[300 + t]);
            float n = tanh_f(gi_s[600 + t] + r * gh_s[600 + t]);
            newet = (1.f - z) * n + z * et_s[t];
        }
        __syncthreads();
        if (t < 300) et_s[t] = newet;
        __syncthreads();
    }

    if (w < 3) {
        const float* wp = dW + w * 300;
        float acc = 0.f;
        for (int k = lane; k < 300; k += 32) acc += wp[k] * et_s[k];
        acc = warpred(acc);
        if (lane == 0) outp[b * 3 + w] = acc + db[w];
    }
}

// ---------------- launch -----------------------------------------------------
extern "C" void kernel_launch(void* const* d_in, const int* in_sizes, int n_in,
                              void* d_out, int out_size) {
    const int*   text      = (const int*)  d_in[0];
    const int*   aspect    = (const int*)  d_in[1];
    const int*   leftc     = (const int*)  d_in[2];
    const float* embedding = (const float*)d_in[3];
    const float* Wih_f     = (const float*)d_in[4];
    const float* Whh_f     = (const float*)d_in[5];
    const float* bih_f     = (const float*)d_in[6];
    const float* bhh_f     = (const float*)d_in[7];
    const float* Wih_b     = (const float*)d_in[8];
    const float* Whh_b     = (const float*)d_in[9];
    const float* bih_b     = (const float*)d_in[10];
    const float* bhh_b     = (const float*)d_in[11];
    const float* att_W     = (const float*)d_in[12];
    const float* gru_Wih   = (const float*)d_in[14];
    const float* gru_Whh   = (const float*)d_in[15];
    const float* gru_bih   = (const float*)d_in[16];
    const float* gru_bhh   = (const float*)d_in[17];
    const float* dense_W   = (const float*)d_in[18];
    const float* dense_b   = (const float*)d_in[19];
    float* outp = (float*)d_out;

    cudaFuncSetAttribute(k_scan8, cudaFuncAttributeMaxDynamicSharedMemorySize,
                         SC8_BYTES);
    cudaFuncSetAttribute(k_gemm_tc, cudaFuncAttributeMaxDynamicSharedMemorySize,
                         GEMM_SMEM_BYTES);

    k_prep<<<B_, 256>>>(text, aspect, leftc);
    k_sort<<<1, B_>>>();
    k_embed<<<(B_ * S_ * 75) / 256, 256>>>(text, embedding);
    k_gemm_tc<<<dim3(B_ * S_ / 128, (G4 + 63) / 64, 2), 256, GEMM_SMEM_BYTES>>>(
        Wih_f, bih_f, Wih_b, bih_b);
    k_scan8<<<dim3(8, 32), 768, SC8_BYTES>>>(Whh_f, bhh_f, Whh_b, bhh_b);
    k_attn<<<B_, 256>>>(att_W);
    k_final2<<<B_, 384>>>(gru_Wih, gru_Whh, gru_bih, gru_bhh, dense_W, dense_b, outp);
}

// round 16
// speedup vs baseline: 1.1041x; 1.0724x over previous
#include <cuda_runtime.h>
#include <math.h>
#include <stdint.h>

#define B_ 128
#define S_ 256
#define E_ 300
#define H_ 300
#define G4 1200   // 4*H
#define DIV 601   // 2H+1
#define NM 38
#define KC 5
#define CHF 60
#define HPAD2 304
#define NB 8
#define TX_BYTES 9600

// ---------------- scratch ----------------------------------------------------
__device__ float g_mem [B_*S_*E_];
__device__ float g_xgf [B_*S_*G4];
__device__ float g_xgb [B_*S_*G4];
__device__ float g_outf[B_*S_*H_];
__device__ float g_outb[B_*S_*H_];
__device__ float g_ivec[B_*DIV];
__device__ int   g_mlen[B_], g_llen[B_], g_alen[B_];
__device__ int   g_perm[B_];

__device__ __forceinline__ float sigm(float x) { return 1.f / (1.f + expf(-x)); }

__device__ __forceinline__ uint32_t smem_u32(const void* p) {
    uint32_t a;
    asm("{ .reg .u64 t; cvta.to.shared.u64 t, %1; cvt.u32.u64 %0, t; }" : "=r"(a) : "l"(p));
    return a;
}
__device__ __forceinline__ unsigned long long pack2(float a, float b) {
    unsigned long long r;
    asm("mov.b64 %0, {%1,%2};" : "=l"(r) : "f"(a), "f"(b));
    return r;
}
__device__ __forceinline__ void fma2(unsigned long long& acc,
                                     unsigned long long a, unsigned long long b) {
    asm("fma.rn.f32x2 %0, %1, %2, %0;" : "+l"(acc) : "l"(a), "l"(b));
}
__device__ __forceinline__ float2 unpack2(unsigned long long v) {
    float2 f;
    asm("mov.b64 {%0,%1}, %2;" : "=f"(f.x), "=f"(f.y) : "l"(v));
    return f;
}
__device__ __forceinline__ void lds2u64(unsigned long long& a, unsigned long long& b,
                                        uint32_t addr) {
    asm volatile("ld.shared.v2.b64 {%0,%1}, [%2];" : "=l"(a), "=l"(b) : "r"(addr));
}
__device__ __forceinline__ float warpred(float v) {
#pragma unroll
    for (int o = 16; o > 0; o >>= 1) v += __shfl_down_sync(0xffffffffu, v, o);
    return v;
}
__device__ __forceinline__ void mbar_wait_cluster(uint32_t mbar, int parity) {
    uint32_t done;
    asm volatile(
        "{\n\t.reg .pred p;\n\t"
        "mbarrier.try_wait.parity.acquire.cluster.shared::cta.b64 p, [%1], %2;\n\t"
        "selp.b32 %0, 1, 0, p;\n\t}"
        : "=r"(done) : "r"(mbar), "r"((uint32_t)parity) : "memory");
    if (!done) {
        asm volatile(
            "{\n\t.reg .pred P1;\n\t"
            "WL_%=:\n\t"
            "mbarrier.try_wait.parity.acquire.cluster.shared::cta.b64 P1, [%0], %1, 0x989680;\n\t"
            "@P1 bra.uni WD_%=;\n\t"
            "bra.uni WL_%=;\n\t"
            "WD_%=:\n\t}"
            :: "r"(mbar), "r"((uint32_t)parity) : "memory");
    }
}
__device__ __forceinline__ uint32_t cvttf(float x) {
    uint32_t r;
    asm("cvt.rna.tf32.f32 %0, %1;" : "=r"(r) : "f"(x));
    return r;
}
__device__ __forceinline__ void mma_tf32(float* c, const uint32_t* a, const uint32_t* b) {
    asm volatile(
        "mma.sync.aligned.m16n8k8.row.col.f32.tf32.tf32.f32 "
        "{%0,%1,%2,%3},{%4,%5,%6,%7},{%8,%9},{%0,%1,%2,%3};"
        : "+f"(c[0]), "+f"(c[1]), "+f"(c[2]), "+f"(c[3])
        : "r"(a[0]), "r"(a[1]), "r"(a[2]), "r"(a[3]), "r"(b[0]), "r"(b[1]));
}

// ---------------- K0: lengths ------------------------------------------------
__global__ void k_prep(const int* __restrict__ text,
                       const int* __restrict__ aspect,
                       const int* __restrict__ leftc) {
    int b = blockIdx.x, t = threadIdx.x;
    int c1 = __syncthreads_count(text[b*S_ + t] != 0);
    int c2 = __syncthreads_count(leftc[b*S_ + t] != 0);
    int c3 = __syncthreads_count(t < 8 && aspect[b*8 + t] != 0);
    if (t == 0) { g_mlen[b] = c1; g_llen[b] = c2; g_alen[b] = c3; }
}

// ---------------- K0b: sort batches by length --------------------------------
__global__ void k_sort() {
    __shared__ int v[B_];
    int t = threadIdx.x;
    v[t] = (g_mlen[t] << 8) | t;
    __syncthreads();
    for (int k = 2; k <= B_; k <<= 1) {
        for (int j = k >> 1; j > 0; j >>= 1) {
            int ixj = t ^ j;
            if (ixj > t) {
                int a = v[t], b = v[ixj];
                bool up = ((t & k) == 0);
                if ((a > b) == up) { v[t] = b; v[ixj] = a; }
            }
            __syncthreads();
        }
    }
    g_perm[t] = v[t] & 255;
}

// ---------------- K1: embedding gather (flat float4 copy) --------------------
__global__ __launch_bounds__(256) void k_embed(const int* __restrict__ text,
                                               const float* __restrict__ emb) {
    int i = blockIdx.x * 256 + threadIdx.x;          // over B*S*75 float4s
    int r = i / 75, c = i - r * 75;
    int id = text[r];
    ((float4*)g_mem)[i] = ((const float4*)(emb + (size_t)id * E_))[c];
}

// ---------------- K2: xg GEMM via tf32 tensor cores (R12-exact) --------------
#define AST 36
#define GEMM_SMEM_U32 (2*128*AST + 2*64*AST)
#define GEMM_SMEM_BYTES  (GEMM_SMEM_U32*4)

__global__ __launch_bounds__(256, 3) void k_gemm_tc(
    const float* __restrict__ Wf, const float* __restrict__ bf,
    const float* __restrict__ Wb, const float* __restrict__ bb_) {
    extern __shared__ uint32_t smg[];
    uint32_t* As = smg;                    // [2][128][AST]  tf32 bits
    uint32_t* Bs = smg + 2*128*AST;        // [2][64][AST]   tf32 bits
    const int N = G4, K = E_;
    const float* A    = g_mem;
    const float* W    = blockIdx.z ? Wb  : Wf;
    const float* bias = blockIdx.z ? bb_ : bf;
    float* C          = blockIdx.z ? g_xgb : g_xgf;

    const int tid  = threadIdx.x;
    const int lane = tid & 31;
    const int warp = tid >> 5;
    const int wm_  = warp >> 1;
    const int wn_  = warp & 1;
    const int m0   = blockIdx.x * 128;
    const int n0   = blockIdx.y * 64;

    const int aRow[4] = { (tid+0*256)>>3, (tid+1*256)>>3, (tid+2*256)>>3, (tid+3*256)>>3 };
    const int aF4 [4] = { (tid+0*256)&7,  (tid+1*256)&7,  (tid+2*256)&7,  (tid+3*256)&7  };
    const int bRow[2] = { (tid+0*256)>>3, (tid+1*256)>>3 };
    const int bF4 [2] = { (tid+0*256)&7,  (tid+1*256)&7  };

    float4 rA[4], rB[2];
    auto ldChunk = [&](int c) {
        int kc0 = c * 32;
#pragma unroll
        for (int j = 0; j < 4; j++) {
            int kk = kc0 + aF4[j]*4;
            rA[j] = (kk < K) ? *(const float4*)(A + (size_t)(m0 + aRow[j]) * K + kk)
                             : make_float4(0.f,0.f,0.f,0.f);
        }
#pragma unroll
        for (int j = 0; j < 2; j++) {
            int kk = kc0 + bF4[j]*4;
            rB[j] = (kk < K && n0 + bRow[j] < N)
                    ? *(const float4*)(W + (size_t)(n0 + bRow[j]) * K + kk)
                    : make_float4(0.f,0.f,0.f,0.f);
        }
    };
    auto stChunk = [&](int buf) {
#pragma unroll
        for (int j = 0; j < 4; j++) {
            uint4 t4 = make_uint4(cvttf(rA[j].x), cvttf(rA[j].y),
                                  cvttf(rA[j].z), cvttf(rA[j].w));
            *(uint4*)(As + (size_t)buf*128*AST + aRow[j]*AST + aF4[j]*4) = t4;
        }
#pragma unroll
        for (int j = 0; j < 2; j++) {
            uint4 t4 = make_uint4(cvttf(rB[j].x), cvttf(rB[j].y),
                                  cvttf(rB[j].z), cvttf(rB[j].w));
            *(uint4*)(Bs + (size_t)buf*64*AST + bRow[j]*AST + bF4[j]*4) = t4;
        }
    };

    float acc[2][4][4];
#pragma unroll
    for (int i = 0; i < 2; i++)
#pragma unroll
        for (int j = 0; j < 4; j++)
#pragma unroll
            for (int k = 0; k < 4; k++) acc[i][j][k] = 0.f;

    ldChunk(0);
    stChunk(0);
    __syncthreads();

    for (int c = 0; c < 10; c++) {
        int cur = c & 1;
        if (c + 1 < 10) ldChunk(c + 1);
        const uint32_t* Ab = As + (size_t)cur*128*AST;
        const uint32_t* Bb = Bs + (size_t)cur*64*AST;
#pragma unroll
        for (int ks = 0; ks < 4; ks++) {
            int kk = ks * 8;
            uint32_t afr[2][4];
#pragma unroll
            for (int tm = 0; tm < 2; tm++) {
                int r  = wm_*32 + tm*16 + (lane >> 2);
                int cc = kk + (lane & 3);
                afr[tm][0] = Ab[r*AST + cc];
                afr[tm][1] = Ab[(r+8)*AST + cc];
                afr[tm][2] = Ab[r*AST + cc + 4];
                afr[tm][3] = Ab[(r+8)*AST + cc + 4];
            }
            uint32_t bfr[4][2];
#pragma unroll
            for (int tn = 0; tn < 4; tn++) {
                int nn = wn_*32 + tn*8 + (lane >> 2);
                int ck = kk + (lane & 3);
                bfr[tn][0] = Bb[nn*AST + ck];
                bfr[tn][1] = Bb[nn*AST + ck + 4];
            }
#pragma unroll
            for (int tm = 0; tm < 2; tm++)
#pragma unroll
                for (int tn = 0; tn < 4; tn++)
                    mma_tf32(acc[tm][tn], afr[tm], bfr[tn]);
        }
        if (c + 1 < 10) stChunk(cur ^ 1);
        __syncthreads();
    }

#pragma unroll
    for (int tm = 0; tm < 2; tm++) {
        int r0 = m0 + wm_*32 + tm*16 + (lane >> 2);
#pragma unroll
        for (int tn = 0; tn < 4; tn++) {
            int cc = n0 + wn_*32 + tn*8 + 2*(lane & 3);
            if (cc < N) {
                float2 v0 = make_float2(acc[tm][tn][0] + bias[cc],
                                        acc[tm][tn][1] + bias[cc+1]);
                float2 v1 = make_float2(acc[tm][tn][2] + bias[cc],
                                        acc[tm][tn][3] + bias[cc+1]);
                *(float2*)(C + (size_t)r0 * N + cc)       = v0;
                *(float2*)(C + (size_t)(r0+8) * N + cc)   = v1;
            }
        }
    }
}

// ---------------- K3: clustered scan (R12 structure; out pre-zeroed) ---------
#define SC8_FLOATS (2*NB*HPAD2 + NB*152 + 152*41 + 152)
#define SC8_BYTES  (SC8_FLOATS*4)

__global__ void __cluster_dims__(8,1,1) __launch_bounds__(768, 1)
k_scan8(const float* __restrict__ Whf, const float* __restrict__ bhf,
        const float* __restrict__ Whb, const float* __restrict__ bhb) {
    extern __shared__ float sm[];
    float* h_s   = sm;                        // [2][8][HPAD2]
    float* xg_s  = h_s + 2*NB*HPAD2;          // [8][152]
    float* g_s   = xg_s + NB*152;             // row*41 + bb*5 + kc
    float* bhh_s = g_s + 152*41;
    __shared__ __align__(8) unsigned long long mbar[2];
    __shared__ int len_s[NB], bset[NB];
    __shared__ int maxlen_s;

    const int rank = blockIdx.x;
    const int grp  = blockIdx.y;
    const int dir  = grp & 1;
    const int gi   = 15 - (grp >> 1);         // LPT order
    const int m0   = rank * NM;
    const int tid  = threadIdx.x;
    const bool act = tid < 760;
    const int kc   = act ? (tid / 152) : 0;
    const int row  = tid % 152;
    const int wg   = row / 38;                // gate-major: coalesced xg
    const int wm   = row - wg * 38;
    const bool wok = act && (m0 + wm < H_);

    const float* Whh = dir ? Whb : Whf;
    const float* bhh = dir ? bhb : bhf;
    const float* xg  = dir ? g_xgb : g_xgf;
    float* out       = dir ? g_outb : g_outf;

    if (tid < NB) {
        int b = g_perm[gi*NB + tid];
        bset[tid]  = b;
        len_s[tid] = g_mlen[b];
    }
    for (int i = tid; i < 2*NB*HPAD2; i += 768) h_s[i] = 0.f;
    if (tid < 152) {
        int g2 = tid / 38, m2 = tid - g2 * 38;
        bhh_s[tid] = (m0 + m2 < H_) ? bhh[g2*300 + m0 + m2] : 0.f;
    }
    const uint32_t mb_base = smem_u32(&mbar[0]);
    if (tid == 0) {
        asm volatile("mbarrier.init.shared.b64 [%0], %1;" :: "r"(mb_base),     "r"(1u) : "memory");
        asm volatile("mbarrier.init.shared.b64 [%0], %1;" :: "r"(mb_base + 8), "r"(1u) : "memory");
    }

    unsigned long long w2[30];
    {
        const float* wr = Whh + (size_t)(wg*300 + m0 + wm) * 300 + kc*CHF;
#pragma unroll
        for (int j = 0; j < 30; j++) {
            float2 v = make_float2(0.f, 0.f);
            if (wok) v = *(const float2*)(wr + 2*j);
            w2[j] = pack2(v.x, v.y);
        }
    }
    __syncthreads();
    if (tid == 0) {
        int mx = len_s[0];
        for (int i = 1; i < NB; i++) mx = max(mx, len_s[i]);
        maxlen_s = mx;
    }
    __syncthreads();
    const int maxlen = maxlen_s;

    asm volatile("barrier.cluster.arrive.aligned;" ::: "memory");
    asm volatile("barrier.cluster.wait.aligned;"   ::: "memory");

    const int p_bb0 = tid / 152;
    const int xcol  = wg*300 + m0 + wm;
    const bool xok  = (tid < 608) && (m0 + wm < H_);

    const int u_bb = tid & 7, u_m = tid >> 3;
    const bool uok = (tid < 304) && (m0 + u_m < H_);
    const int u_L  = len_s[u_bb & (NB-1)];
    const int u_b  = bset[u_bb & (NB-1)];
    const int mg   = m0 + u_m;
    float c_reg = 0.f;

    const uint32_t h_base = smem_u32(h_s);
    int buf = 0;
    int ph[2] = {0, 0};
    for (int t = 0; t < maxlen; t++) {
        const int pn = (t + 1) & 1;
        const uint32_t mb_n = mb_base + (uint32_t)pn * 8u;
        if (tid == 0) {
            asm volatile("mbarrier.arrive.expect_tx.shared.b64 _, [%0], %1;"
                         :: "r"(mb_n), "r"((uint32_t)TX_BYTES) : "memory");
        }
        float xv0 = 0.f, xv1 = 0.f;
        if (xok) {
            int L0 = len_s[p_bb0], L1 = len_s[p_bb0 + 4];
            int s0 = dir ? (L0 - 1 - t) : t; if (s0 < 0) s0 = 0;
            int s1 = dir ? (L1 - 1 - t) : t; if (s1 < 0) s1 = 0;
            xv0 = xg[((size_t)bset[p_bb0    ]*S_ + s0)*G4 + xcol];
            xv1 = xg[((size_t)bset[p_bb0 + 4]*S_ + s1)*G4 + xcol];
        }
        if (act) {
#pragma unroll
            for (int p = 0; p < 2; p++) {
                unsigned long long a0 = 0ull, a1 = 0ull, a2 = 0ull, a3 = 0ull;
                uint32_t hb = h_base + (uint32_t)((buf*NB + 4*p)*HPAD2 + kc*CHF)*4u;
#pragma unroll
                for (int j = 0; j < 15; j++) {
                    unsigned long long q0, q1;
                    lds2u64(q0, q1, hb + j*16);
                    fma2(a0, w2[2*j], q0); fma2(a0, w2[2*j+1], q1);
                    lds2u64(q0, q1, hb + HPAD2*4 + j*16);
                    fma2(a1, w2[2*j], q0); fma2(a1, w2[2*j+1], q1);
                    lds2u64(q0, q1, hb + 2*HPAD2*4 + j*16);
                    fma2(a2, w2[2*j], q0); fma2(a2, w2[2*j+1], q1);
                    lds2u64(q0, q1, hb + 3*HPAD2*4 + j*16);
                    fma2(a3, w2[2*j], q0); fma2(a3, w2[2*j+1], q1);
                }
                float2 f0 = unpack2(a0), f1 = unpack2(a1);
                float2 f2 = unpack2(a2), f3 = unpack2(a3);
                g_s[row*41 + (4*p+0)*5 + kc] = f0.x + f0.y;
                g_s[row*41 + (4*p+1)*5 + kc] = f1.x + f1.y;
                g_s[row*41 + (4*p+2)*5 + kc] = f2.x + f2.y;
                g_s[row*41 + (4*p+3)*5 + kc] = f3.x + f3.y;
            }
        }
        if (tid < 608) {
            xg_s[p_bb0*152 + row]       = xv0;
            xg_s[(p_bb0 + 4)*152 + row] = xv1;
        }
        __syncthreads();
        if (uok) {
            float gv[4];
#pragma unroll
            for (int g = 0; g < 4; g++) {
                int r2 = g*38 + u_m;
                float s_ = xg_s[u_bb*152 + r2] + bhh_s[r2];
#pragma unroll
                for (int k2 = 0; k2 < KC; k2++) s_ += g_s[r2*41 + u_bb*5 + k2];
                gv[g] = s_;
            }
            float hw;
            bool live = (t < u_L);
            if (live) {
                float ig = sigm(gv[0]), fg = sigm(gv[1]);
                float gt = tanhf(gv[2]), og = sigm(gv[3]);
                float cn = fg * c_reg + ig * gt;
                c_reg = cn;
                hw = og * tanhf(cn);
            } else {
                hw = h_s[(buf*NB + u_bb)*HPAD2 + mg];   // hold h; out pre-zeroed
            }
            int nb2 = buf ^ 1;
            uint32_t laddr = smem_u32(&h_s[(nb2*NB + u_bb)*HPAD2 + mg]);
            uint32_t hw_u  = __float_as_uint(hw);
#pragma unroll
            for (int r = 0; r < 8; r++) {
                uint32_t raddr, rmbar;
                asm volatile("mapa.shared::cluster.u32 %0, %1, %2;"
                             : "=r"(raddr) : "r"(laddr), "r"(r));
                asm volatile("mapa.shared::cluster.u32 %0, %1, %2;"
                             : "=r"(rmbar) : "r"(mb_n), "r"(r));
                asm volatile(
                    "st.async.shared::cluster.mbarrier::complete_tx::bytes.b32 [%0], %1, [%2];"
                    :: "r"(raddr), "r"(hw_u), "r"(rmbar) : "memory");
            }
            if (live) {
                int s = dir ? (u_L - 1 - t) : t;
                out[((size_t)u_b*S_ + s)*H_ + mg] = hw;
            }
        }
        mbar_wait_cluster(mb_n, ph[pn]);
        ph[pn] ^= 1;
        buf ^= 1;
    }
    // no tail zero-fill: g_outf/g_outb pre-zeroed by cudaMemsetAsync
}

// ---------------- K4: attention ----------------------------------------------
__global__ __launch_bounds__(256) void k_attn(const float* __restrict__ attW) {
    __shared__ __align__(16) float attw_s[1204];
    __shared__ float aw_s[256];
    __shared__ float au_s[256];
    __shared__ float red[256];
    int b = blockIdx.x, t = threadIdx.x;
    for (int i = t; i < 1201; i += 256) attw_s[i] = attW[i];
    __syncthreads();

    float ml = (float)g_mlen[b], ll = (float)g_llen[b], al = (float)g_alen[b];
    float pos = (float)t;
    float w, u;
    if (pos < ll)                       { w = 1.f - (ll - pos) / ml;            u = pos - ll; }
    else if (pos >= ll + al && pos < ml){ w = 1.f - (pos - ll - al + 1.f) / ml; u = pos - ll - al + 1.f; }
    else                                { w = 1.f; u = 0.f; }

    const float4* rf = (const float4*)(g_outf + ((size_t)b * S_ + t) * H_);
    const float4* rb = (const float4*)(g_outb + ((size_t)b * S_ + t) * H_);
    float dot = 0.f;
#pragma unroll 5
    for (int k = 0; k < 75; k++) {
        float4 a = rf[k]; float4 wv = *(const float4*)&attw_s[4 * k];
        dot += a.x*wv.x + a.y*wv.y + a.z*wv.z + a.w*wv.w;
        float4 c = rb[k]; float4 wv2 = *(const float4*)&attw_s[300 + 4 * k];
        dot += c.x*wv2.x + c.y*wv2.y + c.z*wv2.z + c.w*wv2.w;
    }
    float score = w * dot + u * attw_s[600];

    red[t] = score; __syncthreads();
    for (int off = 128; off > 0; off >>= 1) {
        if (t < off) red[t] = fmaxf(red[t], red[t + off]);
        __syncthreads();
    }
    float mx = red[0]; __syncthreads();
    float e = expf(score - mx);
    red[t] = e; __syncthreads();
    for (int off = 128; off > 0; off >>= 1) {
        if (t < off) red[t] += red[t + off];
        __syncthreads();
    }
    float alpha = e / red[0];
    aw_s[t] = alpha * w;
    au_s[t] = alpha * u;
    __syncthreads();

    for (int d = t; d < DIV; d += 256) {
        float acc = 0.f;
        if (d < 300) {
            const float* p = g_outf + (size_t)b * S_ * H_ + d;
            for (int s = 0; s < S_; s++) acc += aw_s[s] * p[(size_t)s * H_];
        } else if (d < 600) {
            const float* p = g_outb + (size_t)b * S_ * H_ + (d - 300);
            for (int s = 0; s < S_; s++) acc += aw_s[s] * p[(size_t)s * H_];
        } else {
            for (int s = 0; s < S_; s++) acc += au_s[s];
        }
        g_ivec[b * DIV + d] = acc;
    }
}

// ---------------- K5: GRU hops + dense -------------------------------------
__global__ __launch_bounds__(384) void k_final2(
    const float* __restrict__ Wih, const float* __restrict__ Whh,
    const float* __restrict__ bih, const float* __restrict__ bhh,
    const float* __restrict__ dW,  const float* __restrict__ db,
    float* __restrict__ outp) {
    __shared__ float iv_s[DIV];
    __shared__ float et_s[300];
    __shared__ float gi_s[900];
    __shared__ float gh_s[900];
    int b = blockIdx.x, t = threadIdx.x;
    int w = t >> 5, lane = t & 31;

    for (int i = t; i < DIV; i += 384) iv_s[i] = g_ivec[b * DIV + i];
    if (t < 300) et_s[t] = 0.f;
    __syncthreads();

    for (int row = w; row < 900; row += 12) {
        const float* wp = Wih + (size_t)row * DIV;
        float acc = 0.f;
        for (int k = lane; k < DIV; k += 32) acc += wp[k] * iv_s[k];
        acc = warpred(acc);
        if (lane == 0) gi_s[row] = acc + bih[row];
    }
    __syncthreads();

    for (int hop = 0; hop < 3; hop++) {
        for (int row = w; row < 900; row += 12) {
            const float* wp = Whh + (size_t)row * 300;
            float acc = 0.f;
#pragma unroll 2
            for (int k = lane; k < 300; k += 32) acc += wp[k] * et_s[k];
            acc = warpred(acc);
            if (lane == 0) gh_s[row] = acc + bhh[row];
        }
        __syncthreads();
        float newet = 0.f;
        if (t < 300) {
            float r = sigm(gi_s[t]       + gh_s[t]);
            float z = sigm(gi_s[300 + t] + gh_s[300 + t]);
            float n = tanhf(gi_s[600 + t] + r * gh_s[600 + t]);
            newet = (1.f - z) * n + z * et_s[t];
        }
        __syncthreads();
        if (t < 300) et_s[t] = newet;
        __syncthreads();
    }

    if (w < 3) {
        const float* wp = dW + w * 300;
        float acc = 0.f;
        for (int k = lane; k < 300; k += 32) acc += wp[k] * et_s[k];
        acc = warpred(acc);
        if (lane == 0) outp[b * 3 + w] = acc + db[w];
    }
}

// ---------------- launch -----------------------------------------------------
extern "C" void kernel_launch(void* const* d_in, const int* in_sizes, int n_in,
                              void* d_out, int out_size) {
    const int*   text      = (const int*)  d_in[0];
    const int*   aspect    = (const int*)  d_in[1];
    const int*   leftc     = (const int*)  d_in[2];
    const float* embedding = (const float*)d_in[3];
    const float* Wih_f     = (const float*)d_in[4];
    const float* Whh_f     = (const float*)d_in[5];
    const float* bih_f     = (const float*)d_in[6];
    const float* bhh_f     = (const float*)d_in[7];
    const float* Wih_b     = (const float*)d_in[8];
    const float* Whh_b     = (const float*)d_in[9];
    const float* bih_b     = (const float*)d_in[10];
    const float* bhh_b     = (const float*)d_in[11];
    const float* att_W     = (const float*)d_in[12];
    const float* gru_Wih   = (const float*)d_in[14];
    const float* gru_Whh   = (const float*)d_in[15];
    const float* gru_bih   = (const float*)d_in[16];
    const float* gru_bhh   = (const float*)d_in[17];
    const float* dense_W   = (const float*)d_in[18];
    const float* dense_b   = (const float*)d_in[19];
    float* outp = (float*)d_out;

    cudaFuncSetAttribute(k_scan8, cudaFuncAttributeMaxDynamicSharedMemorySize,
                         SC8_BYTES);
    cudaFuncSetAttribute(k_gemm_tc, cudaFuncAttributeMaxDynamicSharedMemorySize,
                         GEMM_SMEM_BYTES);

    // pre-zero LSTM outputs (removes all zero-fill from the scan's critical path)
    void* p_outf = nullptr; void* p_outb = nullptr;
    cudaGetSymbolAddress(&p_outf, g_outf);
    cudaGetSymbolAddress(&p_outb, g_outb);
    cudaMemsetAsync(p_outf, 0, sizeof(float) * B_ * S_ * H_);
    cudaMemsetAsync(p_outb, 0, sizeof(float) * B_ * S_ * H_);

    k_prep<<<B_, 256>>>(text, aspect, leftc);
    k_sort<<<1, B_>>>();
    k_embed<<<(B_ * S_ * 75) / 256, 256>>>(text, embedding);
    k_gemm_tc<<<dim3(B_ * S_ / 128, (G4 + 63) / 64, 2), 256, GEMM_SMEM_BYTES>>>(
        Wih_f, bih_f, Wih_b, bih_b);
    k_scan8<<<dim3(8, 32), 768, SC8_BYTES>>>(Whh_f, bhh_f, Whh_b, bhh_b);
    k_attn<<<B_, 256>>>(att_W);
    k_final2<<<B_, 384>>>(gru_Wih, gru_Whh, gru_bih, gru_bhh, dense_W, dense_b, outp);
}

// round 17
// speedup vs baseline: 1.1093x; 1.0047x over previous
#include <cuda_runtime.h>
#include <math.h>
#include <stdint.h>

#define B_ 128
#define S_ 256
#define E_ 300
#define H_ 300
#define G4 1200   // 4*H
#define DIV 601   // 2H+1
#define NM 38
#define KC 5
#define CHF 60
#define HPAD2 304
#define NB 8
#define TX_BYTES 9600

// ---------------- scratch ----------------------------------------------------
__device__ float g_mem [B_*S_*E_];
__device__ float g_xgf [B_*S_*G4];
__device__ float g_xgb [B_*S_*G4];
__device__ float g_outf[B_*S_*H_];
__device__ float g_outb[B_*S_*H_];
__device__ float g_ivec[B_*DIV];
__device__ int   g_mlen[B_], g_llen[B_], g_alen[B_];
__device__ int   g_perm[B_];

__device__ __forceinline__ float sigm(float x) { return 1.f / (1.f + expf(-x)); }

__device__ __forceinline__ uint32_t smem_u32(const void* p) {
    uint32_t a;
    asm("{ .reg .u64 t; cvta.to.shared.u64 t, %1; cvt.u32.u64 %0, t; }" : "=r"(a) : "l"(p));
    return a;
}
__device__ __forceinline__ unsigned long long pack2(float a, float b) {
    unsigned long long r;
    asm("mov.b64 %0, {%1,%2};" : "=l"(r) : "f"(a), "f"(b));
    return r;
}
__device__ __forceinline__ void fma2(unsigned long long& acc,
                                     unsigned long long a, unsigned long long b) {
    asm("fma.rn.f32x2 %0, %1, %2, %0;" : "+l"(acc) : "l"(a), "l"(b));
}
__device__ __forceinline__ float2 unpack2(unsigned long long v) {
    float2 f;
    asm("mov.b64 {%0,%1}, %2;" : "=f"(f.x), "=f"(f.y) : "l"(v));
    return f;
}
__device__ __forceinline__ void lds2u64(unsigned long long& a, unsigned long long& b,
                                        uint32_t addr) {
    asm volatile("ld.shared.v2.b64 {%0,%1}, [%2];" : "=l"(a), "=l"(b) : "r"(addr));
}
__device__ __forceinline__ float warpred(float v) {
#pragma unroll
    for (int o = 16; o > 0; o >>= 1) v += __shfl_down_sync(0xffffffffu, v, o);
    return v;
}
__device__ __forceinline__ void mbar_wait_cluster(uint32_t mbar, int parity) {
    uint32_t done;
    asm volatile(
        "{\n\t.reg .pred p;\n\t"
        "mbarrier.try_wait.parity.acquire.cluster.shared::cta.b64 p, [%1], %2;\n\t"
        "selp.b32 %0, 1, 0, p;\n\t}"
        : "=r"(done) : "r"(mbar), "r"((uint32_t)parity) : "memory");
    if (!done) {
        asm volatile(
            "{\n\t.reg .pred P1;\n\t"
            "WL_%=:\n\t"
            "mbarrier.try_wait.parity.acquire.cluster.shared::cta.b64 P1, [%0], %1, 0x989680;\n\t"
            "@P1 bra.uni WD_%=;\n\t"
            "bra.uni WL_%=;\n\t"
            "WD_%=:\n\t}"
            :: "r"(mbar), "r"((uint32_t)parity) : "memory");
    }
}
__device__ __forceinline__ uint32_t cvttf(float x) {
    uint32_t r;
    asm("cvt.rna.tf32.f32 %0, %1;" : "=r"(r) : "f"(x));
    return r;
}
__device__ __forceinline__ void mma_tf32(float* c, const uint32_t* a, const uint32_t* b) {
    asm volatile(
        "mma.sync.aligned.m16n8k8.row.col.f32.tf32.tf32.f32 "
        "{%0,%1,%2,%3},{%4,%5,%6,%7},{%8,%9},{%0,%1,%2,%3};"
        : "+f"(c[0]), "+f"(c[1]), "+f"(c[2]), "+f"(c[3])
        : "r"(a[0]), "r"(a[1]), "r"(a[2]), "r"(a[3]), "r"(b[0]), "r"(b[1]));
}
// smem load with literal immediate offset (kills address IMADs)
#define LDSOFF(d, a, off) \
    asm volatile("ld.shared.b32 %0, [%1+%2];" : "=r"(d) : "r"(a), "n"(off))

// ---------------- K0: lengths ------------------------------------------------
__global__ void k_prep(const int* __restrict__ text,
                       const int* __restrict__ aspect,
                       const int* __restrict__ leftc) {
    int b = blockIdx.x, t = threadIdx.x;
    int c1 = __syncthreads_count(text[b*S_ + t] != 0);
    int c2 = __syncthreads_count(leftc[b*S_ + t] != 0);
    int c3 = __syncthreads_count(t < 8 && aspect[b*8 + t] != 0);
    if (t == 0) { g_mlen[b] = c1; g_llen[b] = c2; g_alen[b] = c3; }
}

// ---------------- K0b: sort batches by length --------------------------------
__global__ void k_sort() {
    __shared__ int v[B_];
    int t = threadIdx.x;
    v[t] = (g_mlen[t] << 8) | t;
    __syncthreads();
    for (int k = 2; k <= B_; k <<= 1) {
        for (int j = k >> 1; j > 0; j >>= 1) {
            int ixj = t ^ j;
            if (ixj > t) {
                int a = v[t], b = v[ixj];
                bool up = ((t & k) == 0);
                if ((a > b) == up) { v[t] = b; v[ixj] = a; }
            }
            __syncthreads();
        }
    }
    g_perm[t] = v[t] & 255;
}

// ---------------- K1: embedding gather (flat float4 copy) --------------------
__global__ __launch_bounds__(256) void k_embed(const int* __restrict__ text,
                                               const float* __restrict__ emb) {
    int i = blockIdx.x * 256 + threadIdx.x;          // over B*S*75 float4s
    int r = i / 75, c = i - r * 75;
    int id = text[r];
    ((float4*)g_mem)[i] = ((const float4*)(emb + (size_t)id * E_))[c];
}

// ---------------- K2: xg GEMM via tf32 TC, immediate-offset fragment loads ---
#define AST 36
#define GEMM_SMEM_U32 (2*128*AST + 2*64*AST)
#define GEMM_SMEM_BYTES  (GEMM_SMEM_U32*4)

__global__ __launch_bounds__(256, 3) void k_gemm_tc(
    const float* __restrict__ Wf, const float* __restrict__ bf,
    const float* __restrict__ Wb, const float* __restrict__ bb_) {
    extern __shared__ uint32_t smg[];
    uint32_t* As = smg;                    // [2][128][AST]  tf32 bits
    uint32_t* Bs = smg + 2*128*AST;        // [2][64][AST]   tf32 bits
    const int N = G4, K = E_;
    const float* A    = g_mem;
    const float* W    = blockIdx.z ? Wb  : Wf;
    const float* bias = blockIdx.z ? bb_ : bf;
    float* C          = blockIdx.z ? g_xgb : g_xgf;

    const int tid  = threadIdx.x;
    const int lane = tid & 31;
    const int warp = tid >> 5;
    const int wm_  = warp >> 1;
    const int wn_  = warp & 1;
    const int m0   = blockIdx.x * 128;
    const int n0   = blockIdx.y * 64;

    const int aRow[4] = { (tid+0*256)>>3, (tid+1*256)>>3, (tid+2*256)>>3, (tid+3*256)>>3 };
    const int aF4 [4] = { (tid+0*256)&7,  (tid+1*256)&7,  (tid+2*256)&7,  (tid+3*256)&7  };
    const int bRow[2] = { (tid+0*256)>>3, (tid+1*256)>>3 };
    const int bF4 [2] = { (tid+0*256)&7,  (tid+1*256)&7  };

    float4 rA[4], rB[2];
    auto ldChunk = [&](int c) {
        int kc0 = c * 32;
#pragma unroll
        for (int j = 0; j < 4; j++) {
            int kk = kc0 + aF4[j]*4;
            rA[j] = (kk < K) ? *(const float4*)(A + (size_t)(m0 + aRow[j]) * K + kk)
                             : make_float4(0.f,0.f,0.f,0.f);
        }
#pragma unroll
        for (int j = 0; j < 2; j++) {
            int kk = kc0 + bF4[j]*4;
            rB[j] = (kk < K && n0 + bRow[j] < N)
                    ? *(const float4*)(W + (size_t)(n0 + bRow[j]) * K + kk)
                    : make_float4(0.f,0.f,0.f,0.f);
        }
    };
    auto stChunk = [&](int buf) {
#pragma unroll
        for (int j = 0; j < 4; j++) {
            uint4 t4 = make_uint4(cvttf(rA[j].x), cvttf(rA[j].y),
                                  cvttf(rA[j].z), cvttf(rA[j].w));
            *(uint4*)(As + (size_t)buf*128*AST + aRow[j]*AST + aF4[j]*4) = t4;
        }
#pragma unroll
        for (int j = 0; j < 2; j++) {
            uint4 t4 = make_uint4(cvttf(rB[j].x), cvttf(rB[j].y),
                                  cvttf(rB[j].z), cvttf(rB[j].w));
            *(uint4*)(Bs + (size_t)buf*64*AST + bRow[j]*AST + bF4[j]*4) = t4;
        }
    };

    float acc[2][4][4];
#pragma unroll
    for (int i = 0; i < 2; i++)
#pragma unroll
        for (int j = 0; j < 4; j++)
#pragma unroll
            for (int k = 0; k < 4; k++) acc[i][j][k] = 0.f;

    ldChunk(0);
    stChunk(0);
    __syncthreads();

    const uint32_t As_u = smem_u32(As);
    const uint32_t Bs_u = smem_u32(Bs);
    // per-thread fragment base offsets (element coords: row = w*32 + lane>>2, col = lane&3)
    const uint32_t aoff = (uint32_t)(((wm_*32 + (lane >> 2)) * AST + (lane & 3)) * 4);
    const uint32_t boff = (uint32_t)(((wn_*32 + (lane >> 2)) * AST + (lane & 3)) * 4);

    for (int c = 0; c < 10; c++) {
        int cur = c & 1;
        if (c + 1 < 10) ldChunk(c + 1);
        uint32_t ua = As_u + (uint32_t)cur*(128*AST*4) + aoff;
        uint32_t ub = Bs_u + (uint32_t)cur*(64*AST*4)  + boff;
#pragma unroll
        for (int ks = 0; ks < 4; ks++) {
            uint32_t afr[2][4];
            // tm=0: rows r, r+8 (+1152B); cols cc, cc+4 (+16B)
            LDSOFF(afr[0][0], ua, 0);    LDSOFF(afr[0][1], ua, 1152);
            LDSOFF(afr[0][2], ua, 16);   LDSOFF(afr[0][3], ua, 1168);
            // tm=1: +16 rows = +2304B
            LDSOFF(afr[1][0], ua, 2304); LDSOFF(afr[1][1], ua, 3456);
            LDSOFF(afr[1][2], ua, 2320); LDSOFF(afr[1][3], ua, 3472);
            uint32_t bfr[4][2];
            // tn: +8 rows = +1152B each; second col +16B
            LDSOFF(bfr[0][0], ub, 0);    LDSOFF(bfr[0][1], ub, 16);
            LDSOFF(bfr[1][0], ub, 1152); LDSOFF(bfr[1][1], ub, 1168);
            LDSOFF(bfr[2][0], ub, 2304); LDSOFF(bfr[2][1], ub, 2320);
            LDSOFF(bfr[3][0], ub, 3456); LDSOFF(bfr[3][1], ub, 3472);
#pragma unroll
            for (int tm = 0; tm < 2; tm++)
#pragma unroll
                for (int tn = 0; tn < 4; tn++)
                    mma_tf32(acc[tm][tn], afr[tm], bfr[tn]);
            ua += 32;   // next k-slice: +8 elements
            ub += 32;
        }
        if (c + 1 < 10) stChunk(cur ^ 1);
        __syncthreads();
    }

#pragma unroll
    for (int tm = 0; tm < 2; tm++) {
        int r0 = m0 + wm_*32 + tm*16 + (lane >> 2);
#pragma unroll
        for (int tn = 0; tn < 4; tn++) {
            int cc = n0 + wn_*32 + tn*8 + 2*(lane & 3);
            if (cc < N) {
                float2 v0 = make_float2(acc[tm][tn][0] + bias[cc],
                                        acc[tm][tn][1] + bias[cc+1]);
                float2 v1 = make_float2(acc[tm][tn][2] + bias[cc],
                                        acc[tm][tn][3] + bias[cc+1]);
                *(float2*)(C + (size_t)r0 * N + cc)       = v0;
                *(float2*)(C + (size_t)(r0+8) * N + cc)   = v1;
            }
        }
    }
}

// ---------------- K3: clustered scan (R16-exact; out pre-zeroed) -------------
#define SC8_FLOATS (2*NB*HPAD2 + NB*152 + 152*41 + 152)
#define SC8_BYTES  (SC8_FLOATS*4)

__global__ void __cluster_dims__(8,1,1) __launch_bounds__(768, 1)
k_scan8(const float* __restrict__ Whf, const float* __restrict__ bhf,
        const float* __restrict__ Whb, const float* __restrict__ bhb) {
    extern __shared__ float sm[];
    float* h_s   = sm;                        // [2][8][HPAD2]
    float* xg_s  = h_s + 2*NB*HPAD2;          // [8][152]
    float* g_s   = xg_s + NB*152;             // row*41 + bb*5 + kc
    float* bhh_s = g_s + 152*41;
    __shared__ __align__(8) unsigned long long mbar[2];
    __shared__ int len_s[NB], bset[NB];
    __shared__ int maxlen_s;

    const int rank = blockIdx.x;
    const int grp  = blockIdx.y;
    const int dir  = grp & 1;
    const int gi   = 15 - (grp >> 1);         // LPT order
    const int m0   = rank * NM;
    const int tid  = threadIdx.x;
    const bool act = tid < 760;
    const int kc   = act ? (tid / 152) : 0;
    const int row  = tid % 152;
    const int wg   = row / 38;                // gate-major: coalesced xg
    const int wm   = row - wg * 38;
    const bool wok = act && (m0 + wm < H_);

    const float* Whh = dir ? Whb : Whf;
    const float* bhh = dir ? bhb : bhf;
    const float* xg  = dir ? g_xgb : g_xgf;
    float* out       = dir ? g_outb : g_outf;

    if (tid < NB) {
        int b = g_perm[gi*NB + tid];
        bset[tid]  = b;
        len_s[tid] = g_mlen[b];
    }
    for (int i = tid; i < 2*NB*HPAD2; i += 768) h_s[i] = 0.f;
    if (tid < 152) {
        int g2 = tid / 38, m2 = tid - g2 * 38;
        bhh_s[tid] = (m0 + m2 < H_) ? bhh[g2*300 + m0 + m2] : 0.f;
    }
    const uint32_t mb_base = smem_u32(&mbar[0]);
    if (tid == 0) {
        asm volatile("mbarrier.init.shared.b64 [%0], %1;" :: "r"(mb_base),     "r"(1u) : "memory");
        asm volatile("mbarrier.init.shared.b64 [%0], %1;" :: "r"(mb_base + 8), "r"(1u) : "memory");
    }

    unsigned long long w2[30];
    {
        const float* wr = Whh + (size_t)(wg*300 + m0 + wm) * 300 + kc*CHF;
#pragma unroll
        for (int j = 0; j < 30; j++) {
            float2 v = make_float2(0.f, 0.f);
            if (wok) v = *(const float2*)(wr + 2*j);
            w2[j] = pack2(v.x, v.y);
        }
    }
    __syncthreads();
    if (tid == 0) {
        int mx = len_s[0];
        for (int i = 1; i < NB; i++) mx = max(mx, len_s[i]);
        maxlen_s = mx;
    }
    __syncthreads();
    const int maxlen = maxlen_s;

    asm volatile("barrier.cluster.arrive.aligned;" ::: "memory");
    asm volatile("barrier.cluster.wait.aligned;"   ::: "memory");

    const int p_bb0 = tid / 152;
    const int xcol  = wg*300 + m0 + wm;
    const bool xok  = (tid < 608) && (m0 + wm < H_);

    const int u_bb = tid & 7, u_m = tid >> 3;
    const bool uok = (tid < 304) && (m0 + u_m < H_);
    const int u_L  = len_s[u_bb & (NB-1)];
    const int u_b  = bset[u_bb & (NB-1)];
    const int mg   = m0 + u_m;
    float c_reg = 0.f;

    const uint32_t h_base = smem_u32(h_s);
    int buf = 0;
    int ph[2] = {0, 0};
    for (int t = 0; t < maxlen; t++) {
        const int pn = (t + 1) & 1;
        const uint32_t mb_n = mb_base + (uint32_t)pn * 8u;
        if (tid == 0) {
            asm volatile("mbarrier.arrive.expect_tx.shared.b64 _, [%0], %1;"
                         :: "r"(mb_n), "r"((uint32_t)TX_BYTES) : "memory");
        }
        float xv0 = 0.f, xv1 = 0.f;
        if (xok) {
            int L0 = len_s[p_bb0], L1 = len_s[p_bb0 + 4];
            int s0 = dir ? (L0 - 1 - t) : t; if (s0 < 0) s0 = 0;
            int s1 = dir ? (L1 - 1 - t) : t; if (s1 < 0) s1 = 0;
            xv0 = xg[((size_t)bset[p_bb0    ]*S_ + s0)*G4 + xcol];
            xv1 = xg[((size_t)bset[p_bb0 + 4]*S_ + s1)*G4 + xcol];
        }
        if (act) {
#pragma unroll
            for (int p = 0; p < 2; p++) {
                unsigned long long a0 = 0ull, a1 = 0ull, a2 = 0ull, a3 = 0ull;
                uint32_t hb = h_base + (uint32_t)((buf*NB + 4*p)*HPAD2 + kc*CHF)*4u;
#pragma unroll
                for (int j = 0; j < 15; j++) {
                    unsigned long long q0, q1;
                    lds2u64(q0, q1, hb + j*16);
                    fma2(a0, w2[2*j], q0); fma2(a0, w2[2*j+1], q1);
                    lds2u64(q0, q1, hb + HPAD2*4 + j*16);
                    fma2(a1, w2[2*j], q0); fma2(a1, w2[2*j+1], q1);
                    lds2u64(q0, q1, hb + 2*HPAD2*4 + j*16);
                    fma2(a2, w2[2*j], q0); fma2(a2, w2[2*j+1], q1);
                    lds2u64(q0, q1, hb + 3*HPAD2*4 + j*16);
                    fma2(a3, w2[2*j], q0); fma2(a3, w2[2*j+1], q1);
                }
                float2 f0 = unpack2(a0), f1 = unpack2(a1);
                float2 f2 = unpack2(a2), f3 = unpack2(a3);
                g_s[row*41 + (4*p+0)*5 + kc] = f0.x + f0.y;
                g_s[row*41 + (4*p+1)*5 + kc] = f1.x + f1.y;
                g_s[row*41 + (4*p+2)*5 + kc] = f2.x + f2.y;
                g_s[row*41 + (4*p+3)*5 + kc] = f3.x + f3.y;
            }
        }
        if (tid < 608) {
            xg_s[p_bb0*152 + row]       = xv0;
            xg_s[(p_bb0 + 4)*152 + row] = xv1;
        }
        __syncthreads();
        if (uok) {
            float gv[4];
#pragma unroll
            for (int g = 0; g < 4; g++) {
                int r2 = g*38 + u_m;
                float s_ = xg_s[u_bb*152 + r2] + bhh_s[r2];
#pragma unroll
                for (int k2 = 0; k2 < KC; k2++) s_ += g_s[r2*41 + u_bb*5 + k2];
                gv[g] = s_;
            }
            float hw;
            bool live = (t < u_L);
            if (live) {
                float ig = sigm(gv[0]), fg = sigm(gv[1]);
                float gt = tanhf(gv[2]), og = sigm(gv[3]);
                float cn = fg * c_reg + ig * gt;
                c_reg = cn;
                hw = og * tanhf(cn);
            } else {
                hw = h_s[(buf*NB + u_bb)*HPAD2 + mg];   // hold h; out pre-zeroed
            }
            int nb2 = buf ^ 1;
            uint32_t laddr = smem_u32(&h_s[(nb2*NB + u_bb)*HPAD2 + mg]);
            uint32_t hw_u  = __float_as_uint(hw);
#pragma unroll
            for (int r = 0; r < 8; r++) {
                uint32_t raddr, rmbar;
                asm volatile("mapa.shared::cluster.u32 %0, %1, %2;"
                             : "=r"(raddr) : "r"(laddr), "r"(r));
                asm volatile("mapa.shared::cluster.u32 %0, %1, %2;"
                             : "=r"(rmbar) : "r"(mb_n), "r"(r));
                asm volatile(
                    "st.async.shared::cluster.mbarrier::complete_tx::bytes.b32 [%0], %1, [%2];"
                    :: "r"(raddr), "r"(hw_u), "r"(rmbar) : "memory");
            }
            if (live) {
                int s = dir ? (u_L - 1 - t) : t;
                out[((size_t)u_b*S_ + s)*H_ + mg] = hw;
            }
        }
        mbar_wait_cluster(mb_n, ph[pn]);
        ph[pn] ^= 1;
        buf ^= 1;
    }
    // no tail zero-fill: g_outf/g_outb pre-zeroed by cudaMemsetAsync
}

// ---------------- K4: attention ----------------------------------------------
__global__ __launch_bounds__(256) void k_attn(const float* __restrict__ attW) {
    __shared__ __align__(16) float attw_s[1204];
    __shared__ float aw_s[256];
    __shared__ float au_s[256];
    __shared__ float red[256];
    int b = blockIdx.x, t = threadIdx.x;
    for (int i = t; i < 1201; i += 256) attw_s[i] = attW[i];
    __syncthreads();

    float ml = (float)g_mlen[b], ll = (float)g_llen[b], al = (float)g_alen[b];
    float pos = (float)t;
    float w, u;
    if (pos < ll)                       { w = 1.f - (ll - pos) / ml;            u = pos - ll; }
    else if (pos >= ll + al && pos < ml){ w = 1.f - (pos - ll - al + 1.f) / ml; u = pos - ll - al + 1.f; }
    else                                { w = 1.f; u = 0.f; }

    const float4* rf = (const float4*)(g_outf + ((size_t)b * S_ + t) * H_);
    const float4* rb = (const float4*)(g_outb + ((size_t)b * S_ + t) * H_);
    float dot = 0.f;
#pragma unroll 5
    for (int k = 0; k < 75; k++) {
        float4 a = rf[k]; float4 wv = *(const float4*)&attw_s[4 * k];
        dot += a.x*wv.x + a.y*wv.y + a.z*wv.z + a.w*wv.w;
        float4 c = rb[k]; float4 wv2 = *(const float4*)&attw_s[300 + 4 * k];
        dot += c.x*wv2.x + c.y*wv2.y + c.z*wv2.z + c.w*wv2.w;
    }
    float score = w * dot + u * attw_s[600];

    red[t] = score; __syncthreads();
    for (int off = 128; off > 0; off >>= 1) {
        if (t < off) red[t] = fmaxf(red[t], red[t + off]);
        __syncthreads();
    }
    float mx = red[0]; __syncthreads();
    float e = expf(score - mx);
    red[t] = e; __syncthreads();
    for (int off = 128; off > 0; off >>= 1) {
        if (t < off) red[t] += red[t + off];
        __syncthreads();
    }
    float alpha = e / red[0];
    aw_s[t] = alpha * w;
    au_s[t] = alpha * u;
    __syncthreads();

    for (int d = t; d < DIV; d += 256) {
        float acc = 0.f;
        if (d < 300) {
            const float* p = g_outf + (size_t)b * S_ * H_ + d;
            for (int s = 0; s < S_; s++) acc += aw_s[s] * p[(size_t)s * H_];
        } else if (d < 600) {
            const float* p = g_outb + (size_t)b * S_ * H_ + (d - 300);
            for (int s = 0; s < S_; s++) acc += aw_s[s] * p[(size_t)s * H_];
        } else {
            for (int s = 0; s < S_; s++) acc += au_s[s];
        }
        g_ivec[b * DIV + d] = acc;
    }
}

// ---------------- K5: GRU hops + dense -------------------------------------
__global__ __launch_bounds__(384) void k_final2(
    const float* __restrict__ Wih, const float* __restrict__ Whh,
    const float* __restrict__ bih, const float* __restrict__ bhh,
    const float* __restrict__ dW,  const float* __restrict__ db,
    float* __restrict__ outp) {
    __shared__ float iv_s[DIV];
    __shared__ float et_s[300];
    __shared__ float gi_s[900];
    __shared__ float gh_s[900];
    int b = blockIdx.x, t = threadIdx.x;
    int w = t >> 5, lane = t & 31;

    for (int i = t; i < DIV; i += 384) iv_s[i] = g_ivec[b * DIV + i];
    if (t < 300) et_s[t] = 0.f;
    __syncthreads();

    for (int row = w; row < 900; row += 12) {
        const float* wp = Wih + (size_t)row * DIV;
        float acc = 0.f;
        for (int k = lane; k < DIV; k += 32) acc += wp[k] * iv_s[k];
        acc = warpred(acc);
        if (lane == 0) gi_s[row] = acc + bih[row];
    }
    __syncthreads();

    for (int hop = 0; hop < 3; hop++) {
        for (int row = w; row < 900; row += 12) {
            const float* wp = Whh + (size_t)row * 300;
            float acc = 0.f;
#pragma unroll 2
            for (int k = lane; k < 300; k += 32) acc += wp[k] * et_s[k];
            acc = warpred(acc);
            if (lane == 0) gh_s[row] = acc + bhh[row];
        }
        __syncthreads();
        float newet = 0.f;
        if (t < 300) {
            float r = sigm(gi_s[t]       + gh_s[t]);
            float z = sigm(gi_s[300 + t] + gh_s[300 + t]);
            float n = tanhf(gi_s[600 + t] + r * gh_s[600 + t]);
            newet = (1.f - z) * n + z * et_s[t];
        }
        __syncthreads();
        if (t < 300) et_s[t] = newet;
        __syncthreads();
    }

    if (w < 3) {
        const float* wp = dW + w * 300;
        float acc = 0.f;
        for (int k = lane; k < 300; k += 32) acc += wp[k] * et_s[k];
        acc = warpred(acc);
        if (lane == 0) outp[b * 3 + w] = acc + db[w];
    }
}

// ---------------- launch -----------------------------------------------------
extern "C" void kernel_launch(void* const* d_in, const int* in_sizes, int n_in,
                              void* d_out, int out_size) {
    const int*   text      = (const int*)  d_in[0];
    const int*   aspect    = (const int*)  d_in[1];
    const int*   leftc     = (const int*)  d_in[2];
    const float* embedding = (const float*)d_in[3];
    const float* Wih_f     = (const float*)d_in[4];
    const float* Whh_f     = (const float*)d_in[5];
    const float* bih_f     = (const float*)d_in[6];
    const float* bhh_f     = (const float*)d_in[7];
    const float* Wih_b     = (const float*)d_in[8];
    const float* Whh_b     = (const float*)d_in[9];
    const float* bih_b     = (const float*)d_in[10];
    const float* bhh_b     = (const float*)d_in[11];
    const float* att_W     = (const float*)d_in[12];
    const float* gru_Wih   = (const float*)d_in[14];
    const float* gru_Whh   = (const float*)d_in[15];
    const float* gru_bih   = (const float*)d_in[16];
    const float* gru_bhh   = (const float*)d_in[17];
    const float* dense_W   = (const float*)d_in[18];
    const float* dense_b   = (const float*)d_in[19];
    float* outp = (float*)d_out;

    cudaFuncSetAttribute(k_scan8, cudaFuncAttributeMaxDynamicSharedMemorySize,
                         SC8_BYTES);
    cudaFuncSetAttribute(k_gemm_tc, cudaFuncAttributeMaxDynamicSharedMemorySize,
                         GEMM_SMEM_BYTES);

    // pre-zero LSTM outputs (removes all zero-fill from the scan's critical path)
    void* p_outf = nullptr; void* p_outb = nullptr;
    cudaGetSymbolAddress(&p_outf, g_outf);
    cudaGetSymbolAddress(&p_outb, g_outb);
    cudaMemsetAsync(p_outf, 0, sizeof(float) * B_ * S_ * H_);
    cudaMemsetAsync(p_outb, 0, sizeof(float) * B_ * S_ * H_);

    k_prep<<<B_, 256>>>(text, aspect, leftc);
    k_sort<<<1, B_>>>();
    k_embed<<<(B_ * S_ * 75) / 256, 256>>>(text, embedding);
    k_gemm_tc<<<dim3(B_ * S_ / 128, (G4 + 63) / 64, 2), 256, GEMM_SMEM_BYTES>>>(
        Wih_f, bih_f, Wih_b, bih_b);
    k_scan8<<<dim3(8, 32), 768, SC8_BYTES>>>(Whh_f, bhh_f, Whh_b, bhh_b);
    k_attn<<<B_, 256>>>(att_W);
    k_final2<<<B_, 384>>>(gru_Wih, gru_Whh, gru_bih, gru_bhh, dense_W, dense_b, outp);
}